// round 1
// baseline (speedup 1.0000x reference)
#include <cuda_runtime.h>
#include <mma.h>

using namespace nvcuda;

// Problem constants
#define BB    8
#define NVOX  16384          // Z*H*W = 16*32*32
#define CC    512
#define C8    64
#define QKVN  192            // q|k|v concatenated columns

// ---------------------------------------------------------------------------
// Scratch (device globals; no runtime allocation allowed)
// ---------------------------------------------------------------------------
__device__ float g_qkv[BB * NVOX * QKVN];       // ~100.7 MB
__device__ float g_spart[BB * 64 * 64 * 64];    // split-K partials for s (8 MB)
__device__ float g_beta[BB * 64 * 64];          // softmax(s)
__device__ float g_Ag[BB * NVOX * C8];          // permuted A = v@beta (33.5 MB)

__device__ float g_W1hi[CC * QKVN], g_W1lo[CC * QKVN], g_b1[QKVN];   // BN1-folded QKV weights (tf32 split)
__device__ float g_W2hi[C8 * CC],  g_W2lo[C8 * CC],  g_b2[CC];       // BN2-folded proj weights (tf32 split)

__device__ __forceinline__ float tf32r(float x) {
    unsigned r;
    asm("cvt.rna.tf32.f32 %0, %1;" : "=r"(r) : "f"(x));
    return __uint_as_float(r);
}

// ---------------------------------------------------------------------------
// K0: fold BN1 into [wq|wk|wv], BN2 into wp; split everything into tf32 hi/lo
// ---------------------------------------------------------------------------
__global__ __launch_bounds__(512) void prep_kernel(
    const float* __restrict__ g1, const float* __restrict__ be1,
    const float* __restrict__ m1, const float* __restrict__ v1,
    const float* __restrict__ wq, const float* __restrict__ bq,
    const float* __restrict__ wk, const float* __restrict__ bk,
    const float* __restrict__ wv, const float* __restrict__ bv,
    const float* __restrict__ wp, const float* __restrict__ bp,
    const float* __restrict__ g2, const float* __restrict__ be2,
    const float* __restrict__ m2, const float* __restrict__ v2)
{
    __shared__ float a1[CC], t1[CC];
    const int tid = threadIdx.x;

    // BN1 affine: img = x*a1 + t1
    a1[tid] = g1[tid] * rsqrtf(v1[tid] + 1e-3f);
    t1[tid] = be1[tid] - m1[tid] * a1[tid];
    __syncthreads();

    // W1'[c,j] = a1[c] * w_sel[c,j]  (row-major K=512 x N=192), tf32 hi/lo split
    for (int idx = tid; idx < CC * QKVN; idx += 512) {
        int c = idx / QKVN, j = idx % QKVN;
        float w = (j < 64) ? wq[c * 64 + j]
                : (j < 128) ? wk[c * 64 + (j - 64)]
                            : wv[c * 64 + (j - 128)];
        float wp2 = a1[c] * w;
        float hi = tf32r(wp2);
        g_W1hi[idx] = hi;
        g_W1lo[idx] = tf32r(wp2 - hi);
    }
    // b1[j] = b_sel[j] + sum_c t1[c]*w_sel[c,j]
    if (tid < QKVN) {
        int j = tid;
        float base = (j < 64) ? bq[j] : (j < 128) ? bk[j - 64] : bv[j - 128];
        float s = 0.f;
        for (int c = 0; c < CC; c++) {
            float w = (j < 64) ? wq[c * 64 + j]
                    : (j < 128) ? wk[c * 64 + (j - 64)]
                                : wv[c * 64 + (j - 128)];
            s += t1[c] * w;
        }
        g_b1[j] = base + s;
    }
    __syncthreads();

    // BN2 affine (reuse smem): out = y*a2 + t2
    a1[tid] = g2[tid] * rsqrtf(v2[tid] + 1e-3f);
    t1[tid] = be2[tid] - m2[tid] * a1[tid];
    __syncthreads();

    // W2'[d,c] = wp[d,c]*a2[c]  (row-major K=64 x N=512)
    for (int idx = tid; idx < C8 * CC; idx += 512) {
        int c = idx & (CC - 1);
        float wpr = wp[idx] * a1[c];
        float hi = tf32r(wpr);
        g_W2hi[idx] = hi;
        g_W2lo[idx] = tf32r(wpr - hi);
    }
    g_b2[tid] = bp[tid] * a1[tid] + t1[tid];
}

// ---------------------------------------------------------------------------
// K1: tf32x3 (split) GEMM:  C[M x N] = A[M x K] * (Bhi + Blo) + bias
//   STAGE 0: A = x (lda=512), K=512, B=g_W1*, N=192, C = g_qkv
//   STAGE 1: A = g_Ag (lda=64), K=64,  B=g_W2*, N=512, C = d_out
// Block tile 128x64, K-chunk 16, 8 warps (4m x 2n), warp tile 32x32.
// ---------------------------------------------------------------------------
template <int STAGE>
__global__ __launch_bounds__(256) void gemm3x_kernel(
    const float* __restrict__ Aext, float* __restrict__ Cext)
{
    constexpr int LDA = (STAGE == 0) ? CC : C8;
    constexpr int K   = (STAGE == 0) ? CC : C8;
    constexpr int LDB = (STAGE == 0) ? QKVN : CC;
    constexpr int LDC = LDB;

    const float* A    = (STAGE == 0) ? Aext   : g_Ag;
    float*       C    = (STAGE == 0) ? g_qkv  : Cext;
    const float* Bhi  = (STAGE == 0) ? g_W1hi : g_W2hi;
    const float* Blo  = (STAGE == 0) ? g_W1lo : g_W2lo;
    const float* bias = (STAGE == 0) ? g_b1   : g_b2;

    __shared__ union U {
        struct S {
            float Ah[128 * 20];
            float Al[128 * 20];
            float Bh[16 * 68];
            float Bl[16 * 68];
        } s;
        float Ct[128 * 64];
    } sm;

    const int tid = threadIdx.x;
    const int n0 = blockIdx.x * 64;    // n fastest -> same m-tile blocks adjacent (L2 reuse of A)
    const int m0 = blockIdx.y * 128;
    const int wid = tid >> 5;
    const int wm = wid & 3;
    const int wn = wid >> 2;

    wmma::fragment<wmma::accumulator, 16, 16, 8, float> acc[2][2];
#pragma unroll
    for (int i = 0; i < 2; i++)
#pragma unroll
        for (int j = 0; j < 2; j++) wmma::fill_fragment(acc[i][j], 0.0f);

    for (int kc = 0; kc < K; kc += 16) {
        __syncthreads();
        // A chunk 128x16 -> split into hi/lo tf32
#pragma unroll
        for (int i = 0; i < 8; i++) {
            int idx = tid + i * 256;
            int r = idx >> 4, c = idx & 15;
            float v = A[(size_t)(m0 + r) * LDA + kc + c];
            float hi = tf32r(v);
            sm.s.Ah[r * 20 + c] = hi;
            sm.s.Al[r * 20 + c] = tf32r(v - hi);
        }
        // B chunk 16x64 (pre-split)
#pragma unroll
        for (int i = 0; i < 4; i++) {
            int idx = tid + i * 256;
            int r = idx >> 6, c = idx & 63;
            size_t g = (size_t)(kc + r) * LDB + n0 + c;
            sm.s.Bh[r * 68 + c] = Bhi[g];
            sm.s.Bl[r * 68 + c] = Blo[g];
        }
        __syncthreads();

#pragma unroll
        for (int k8 = 0; k8 < 2; k8++) {
            wmma::fragment<wmma::matrix_a, 16, 16, 8, wmma::precision::tf32, wmma::row_major> ah[2], al[2];
            wmma::fragment<wmma::matrix_b, 16, 16, 8, wmma::precision::tf32, wmma::row_major> bh[2], bl[2];
#pragma unroll
            for (int mi = 0; mi < 2; mi++) {
                wmma::load_matrix_sync(ah[mi], &sm.s.Ah[(wm * 32 + mi * 16) * 20 + k8 * 8], 20);
                wmma::load_matrix_sync(al[mi], &sm.s.Al[(wm * 32 + mi * 16) * 20 + k8 * 8], 20);
            }
#pragma unroll
            for (int ni = 0; ni < 2; ni++) {
                wmma::load_matrix_sync(bh[ni], &sm.s.Bh[(k8 * 8) * 68 + wn * 32 + ni * 16], 68);
                wmma::load_matrix_sync(bl[ni], &sm.s.Bl[(k8 * 8) * 68 + wn * 32 + ni * 16], 68);
            }
#pragma unroll
            for (int mi = 0; mi < 2; mi++)
#pragma unroll
                for (int ni = 0; ni < 2; ni++) {
                    wmma::mma_sync(acc[mi][ni], ah[mi], bh[ni], acc[mi][ni]);
                    wmma::mma_sync(acc[mi][ni], ah[mi], bl[ni], acc[mi][ni]);
                    wmma::mma_sync(acc[mi][ni], al[mi], bh[ni], acc[mi][ni]);
                }
        }
    }

    __syncthreads();
#pragma unroll
    for (int mi = 0; mi < 2; mi++)
#pragma unroll
        for (int ni = 0; ni < 2; ni++)
            wmma::store_matrix_sync(&sm.Ct[(wm * 32 + mi * 16) * 64 + wn * 32 + ni * 16],
                                    acc[mi][ni], 64, wmma::mem_row_major);
    __syncthreads();
#pragma unroll
    for (int i = 0; i < 32; i++) {
        int idx = tid + i * 256;
        int r = idx >> 6, c = idx & 63;
        C[(size_t)(m0 + r) * LDC + n0 + c] = sm.Ct[idx] + bias[n0 + c];
    }
}

// ---------------------------------------------------------------------------
// K2: s partials, fp32 split-K.  s[b,i,j] = sum_n q[b,n,i]*k[b,n,j]
// grid (64 slices, 8 batches), each block reduces 256 n's, 64x64 outputs.
// ---------------------------------------------------------------------------
__global__ __launch_bounds__(256) void s_partial_kernel()
{
    const int sl = blockIdx.x, b = blockIdx.y;
    __shared__ float sq[64][65], sk[64][65];
    const int tid = threadIdx.x;
    const int jj = tid & 63;
    const int ig = tid >> 6;   // 0..3 -> i block of 16

    float acc[16];
#pragma unroll
    for (int u = 0; u < 16; u++) acc[u] = 0.f;

    for (int c4 = 0; c4 < 4; c4++) {
        int nb = sl * 256 + c4 * 64;
        __syncthreads();
#pragma unroll
        for (int i = 0; i < 16; i++) {
            int idx = tid + i * 256;
            int r = idx >> 6, c = idx & 63;
            const float* row = g_qkv + (size_t)(b * NVOX + nb + r) * QKVN;
            sq[r][c] = row[c];
            sk[r][c] = row[64 + c];
        }
        __syncthreads();
        for (int n = 0; n < 64; n++) {
            float kv = sk[n][jj];
#pragma unroll
            for (int u = 0; u < 16; u++)
                acc[u] += sq[n][ig * 16 + u] * kv;
        }
    }
#pragma unroll
    for (int u = 0; u < 16; u++) {
        int i = ig * 16 + u;
        g_spart[(((b * 64 + sl) * 64) + i) * 64 + jj] = acc[u];
    }
}

// ---------------------------------------------------------------------------
// K3: deterministic reduce of partials + row softmax (axis j)
// grid (64 rows i, 8 batches), 64 threads (one per j)
// ---------------------------------------------------------------------------
__global__ __launch_bounds__(64) void softmax_kernel()
{
    const int i = blockIdx.x, b = blockIdx.y;
    const int j = threadIdx.x;
    float s = 0.f;
    for (int sl = 0; sl < 64; sl++)
        s += g_spart[(((b * 64 + sl) * 64) + i) * 64 + j];

    __shared__ float red[64];
    red[j] = s; __syncthreads();
    for (int o = 32; o > 0; o >>= 1) { if (j < o) red[j] = fmaxf(red[j], red[j + o]); __syncthreads(); }
    float mx = red[0]; __syncthreads();
    float e = expf(s - mx);
    red[j] = e; __syncthreads();
    for (int o = 32; o > 0; o >>= 1) { if (j < o) red[j] += red[j + o]; __syncthreads(); }
    g_beta[((b * 64 + i) * 64) + j] = e / red[0];
}

// ---------------------------------------------------------------------------
// K4: A = v @ beta, stored pre-permuted for the reshape:
//   A_g[b, p, d] = A[b, n, i]  with  p = (i<<8)|(n>>6), d = n&63
// grid (256 n-blocks of 64, 8 batches)
// ---------------------------------------------------------------------------
__global__ __launch_bounds__(256) void av_kernel()
{
    const int b = blockIdx.y;
    const int n0 = blockIdx.x * 64;
    __shared__ float sv[64][65];
    __shared__ float sb[64][64];
    const int tid = threadIdx.x;

#pragma unroll
    for (int i = 0; i < 16; i++) {
        int idx = tid + i * 256;
        int r = idx >> 6, c = idx & 63;
        sv[r][c] = g_qkv[(size_t)(b * NVOX + n0 + r) * QKVN + 128 + c];
        sb[r][c] = g_beta[(b * 64 + r) * 64 + c];
    }
    __syncthreads();

    const int lane = tid & 31;
    const int w = tid >> 5;           // 8 warps, each owns 8 i's
#pragma unroll
    for (int ii = 0; ii < 8; ii++) {
        int i = w * 8 + ii;
#pragma unroll
        for (int h = 0; h < 2; h++) {
            int n = h * 32 + lane;
            float acc = 0.f;
#pragma unroll
            for (int m = 0; m < 64; m++)
                acc += sv[n][m] * sb[m][i];
            int ng = n0 + n;
            int p = (i << 8) | (ng >> 6);
            int d = ng & 63;
            g_Ag[(size_t)(b * NVOX + p) * C8 + d] = acc;  // coalesced (d follows lane)
        }
    }
}

// ---------------------------------------------------------------------------
extern "C" void kernel_launch(void* const* d_in, const int* in_sizes, int n_in,
                              void* d_out, int out_size)
{
    const float* x   = (const float*)d_in[0];
    const float* g1  = (const float*)d_in[1];
    const float* be1 = (const float*)d_in[2];
    const float* m1  = (const float*)d_in[3];
    const float* v1  = (const float*)d_in[4];
    const float* wq  = (const float*)d_in[5];
    const float* bq  = (const float*)d_in[6];
    const float* wk  = (const float*)d_in[7];
    const float* bk  = (const float*)d_in[8];
    const float* wv  = (const float*)d_in[9];
    const float* bv  = (const float*)d_in[10];
    const float* wp  = (const float*)d_in[11];
    const float* bp  = (const float*)d_in[12];
    const float* g2  = (const float*)d_in[13];
    const float* be2 = (const float*)d_in[14];
    const float* m2  = (const float*)d_in[15];
    const float* v2  = (const float*)d_in[16];
    float* out = (float*)d_out;

    prep_kernel<<<1, 512>>>(g1, be1, m1, v1, wq, bq, wk, bk, wv, bv,
                            wp, bp, g2, be2, m2, v2);

    // QKV GEMM: M = 131072, K = 512, N = 192  (n-dim fastest for L2 reuse of x)
    gemm3x_kernel<0><<<dim3(QKVN / 64, (BB * NVOX) / 128), 256>>>(x, nullptr);

    // s partials + softmax
    s_partial_kernel<<<dim3(64, BB), 256>>>();
    softmax_kernel<<<dim3(64, BB), 64>>>();

    // A = v @ beta (pre-permuted)
    av_kernel<<<dim3(NVOX / 64, BB), 256>>>();

    // proj GEMM: M = 131072, K = 64, N = 512 (+ folded BN2) -> final output
    gemm3x_kernel<1><<<dim3(CC / 64, (BB * NVOX) / 128), 256>>>(nullptr, out);
}

// round 2
// speedup vs baseline: 1.1062x; 1.1062x over previous
#include <cuda_runtime.h>
#include <mma.h>

using namespace nvcuda;

// Problem constants
#define BB    8
#define NVOX  16384          // Z*H*W = 16*32*32
#define CC    512
#define C8    64
#define QKVN  192            // q|k|v concatenated columns

// ---------------------------------------------------------------------------
// Scratch (device globals; no runtime allocation allowed)
// ---------------------------------------------------------------------------
__device__ float g_qkv[BB * NVOX * QKVN];       // ~100.7 MB
__device__ float g_spart[BB * 64 * 64 * 64];    // split-K partials for s (8 MB)
__device__ float g_beta[BB * 64 * 64];          // softmax(s)
__device__ float g_Ag[BB * NVOX * C8];          // permuted A = v@beta (33.5 MB)

__device__ float g_W1hi[CC * QKVN], g_W1lo[CC * QKVN], g_b1[QKVN];   // BN1-folded QKV (tf32 split)
__device__ float g_W2hi[C8 * CC],  g_W2lo[C8 * CC],  g_b2[CC];       // BN2-folded proj (tf32 split)

__device__ __forceinline__ float tf32r(float x) {
    unsigned r;
    asm("cvt.rna.tf32.f32 %0, %1;" : "=r"(r) : "f"(x));
    return __uint_as_float(r);
}

__device__ __forceinline__ void cpasync16(void* smem_dst, const void* gsrc) {
    unsigned s = (unsigned)__cvta_generic_to_shared(smem_dst);
    asm volatile("cp.async.cg.shared.global [%0], [%1], 16;\n" :: "r"(s), "l"(gsrc));
}
__device__ __forceinline__ void cpcommit() { asm volatile("cp.async.commit_group;\n"); }
__device__ __forceinline__ void cpwait0()  { asm volatile("cp.async.wait_group 0;\n"); }

// ---------------------------------------------------------------------------
// K0: fold BN1 into [wq|wk|wv], BN2 into wp; split everything into tf32 hi/lo
// ---------------------------------------------------------------------------
__global__ __launch_bounds__(512) void prep_kernel(
    const float* __restrict__ g1, const float* __restrict__ be1,
    const float* __restrict__ m1, const float* __restrict__ v1,
    const float* __restrict__ wq, const float* __restrict__ bq,
    const float* __restrict__ wk, const float* __restrict__ bk,
    const float* __restrict__ wv, const float* __restrict__ bv,
    const float* __restrict__ wp, const float* __restrict__ bp,
    const float* __restrict__ g2, const float* __restrict__ be2,
    const float* __restrict__ m2, const float* __restrict__ v2)
{
    __shared__ float a1[CC], t1[CC];
    const int tid = threadIdx.x;

    a1[tid] = g1[tid] * rsqrtf(v1[tid] + 1e-3f);
    t1[tid] = be1[tid] - m1[tid] * a1[tid];
    __syncthreads();

    for (int idx = tid; idx < CC * QKVN; idx += 512) {
        int c = idx / QKVN, j = idx % QKVN;
        float w = (j < 64) ? wq[c * 64 + j]
                : (j < 128) ? wk[c * 64 + (j - 64)]
                            : wv[c * 64 + (j - 128)];
        float wp2 = a1[c] * w;
        float hi = tf32r(wp2);
        g_W1hi[idx] = hi;
        g_W1lo[idx] = tf32r(wp2 - hi);
    }
    if (tid < QKVN) {
        int j = tid;
        float base = (j < 64) ? bq[j] : (j < 128) ? bk[j - 64] : bv[j - 128];
        float s = 0.f;
        for (int c = 0; c < CC; c++) {
            float w = (j < 64) ? wq[c * 64 + j]
                    : (j < 128) ? wk[c * 64 + (j - 64)]
                                : wv[c * 64 + (j - 128)];
            s += t1[c] * w;
        }
        g_b1[j] = base + s;
    }
    __syncthreads();

    a1[tid] = g2[tid] * rsqrtf(v2[tid] + 1e-3f);
    t1[tid] = be2[tid] - m2[tid] * a1[tid];
    __syncthreads();

    for (int idx = tid; idx < C8 * CC; idx += 512) {
        int c = idx & (CC - 1);
        float wpr = wp[idx] * a1[c];
        float hi = tf32r(wpr);
        g_W2hi[idx] = hi;
        g_W2lo[idx] = tf32r(wpr - hi);
    }
    g_b2[tid] = bp[tid] * a1[tid] + t1[tid];
}

// ---------------------------------------------------------------------------
// K1: pipelined tf32x3 GEMM, double-buffered smem, cp.async B panels.
//   STAGE 0: A = x (131072x512), B = W1 (512x192), C = g_qkv. Block 128x192.
//   STAGE 1: A = g_Ag (131072x64), B = W2 (64x512), C = out.   Block 128x128.
// 8 warps as 4m x 2n. K-chunk = 16.
// ---------------------------------------------------------------------------
template <int STAGE>
__global__ __launch_bounds__(256, 1) void gemm3x_pipe(
    const float* __restrict__ Aext, float* __restrict__ Cext)
{
    constexpr int LDA = (STAGE == 0) ? CC : C8;
    constexpr int K   = (STAGE == 0) ? CC : C8;
    constexpr int BN  = (STAGE == 0) ? QKVN : 128;     // block n width
    constexpr int LDB = (STAGE == 0) ? QKVN : CC;
    constexpr int LDC = LDB;
    constexpr int T   = K / 16;                        // 32 / 4 chunks
    constexpr int SA  = 128 * 20;                      // A panel floats (hi or lo)
    constexpr int SBS = BN + 8;                        // B smem stride (200 / 136)
    constexpr int SB  = 16 * SBS;
    constexpr int BUF = 2 * SA + 2 * SB;               // floats per pipeline buffer
    constexpr int WN  = BN / 2;                        // warp n width (96 / 64)
    constexpr int NF  = WN / 16;                       // n-frags per warp (6 / 4)
    constexpr int NF4 = BN / 4;                        // float4s per n row
    constexpr int CTS = BN + 4;                        // Ct stride

    const float* A    = (STAGE == 0) ? Aext   : g_Ag;
    float*       C    = (STAGE == 0) ? g_qkv  : Cext;
    const float* Bhi  = (STAGE == 0) ? g_W1hi : g_W2hi;
    const float* Blo  = (STAGE == 0) ? g_W1lo : g_W2lo;
    const float* bias = (STAGE == 0) ? g_b1   : g_b2;

    extern __shared__ float sm[];

    const int tid = threadIdx.x;
    const int n0 = (STAGE == 0) ? 0 : blockIdx.x * BN;
    const int m0 = ((STAGE == 0) ? blockIdx.x : blockIdx.y) * 128;
    const int wid = tid >> 5;
    const int wm = wid & 3;
    const int wn = wid >> 2;

    // A staging regs (one chunk ahead)
    const int ar = tid >> 1;           // row 0..127
    const int ac = (tid & 1) * 8;      // col 0 or 8
    float4 a0, a1;

    // B cp.async mapping
    constexpr int BF4  = 16 * (BN / 4);    // float4s per B matrix chunk (768 / 512)
    constexpr int BITR = BF4 / 256;        // per-thread f4 count (3 / 2)

    auto loadA = [&](int kc) {
        const float4* p = (const float4*)(A + (size_t)(m0 + ar) * LDA + kc + ac);
        a0 = p[0]; a1 = p[1];
    };
    auto storeA = [&](float* buf) {
        float v[8] = {a0.x, a0.y, a0.z, a0.w, a1.x, a1.y, a1.z, a1.w};
        float* Ah = buf;
        float* Al = buf + SA;
#pragma unroll
        for (int j = 0; j < 8; j++) {
            float hi = tf32r(v[j]);
            Ah[ar * 20 + ac + j] = hi;
            Al[ar * 20 + ac + j] = tf32r(v[j] - hi);
        }
    };
    auto issueB = [&](int kc, float* buf) {
        float* Bh = buf + 2 * SA;
        float* Bl = buf + 2 * SA + SB;
#pragma unroll
        for (int i = 0; i < BITR; i++) {
            int lin = tid + i * 256;
            int r = lin / (BN / 4);
            int c4 = lin % (BN / 4);
            size_t g = (size_t)(kc + r) * LDB + n0 + c4 * 4;
            cpasync16(&Bh[r * SBS + c4 * 4], &Bhi[g]);
            cpasync16(&Bl[r * SBS + c4 * 4], &Blo[g]);
        }
    };

    wmma::fragment<wmma::accumulator, 16, 16, 8, float> acc[2][NF];
#pragma unroll
    for (int i = 0; i < 2; i++)
#pragma unroll
        for (int j = 0; j < NF; j++) wmma::fill_fragment(acc[i][j], 0.0f);

    // prologue: chunk 0
    loadA(0);
    issueB(0, sm);
    cpcommit();
    storeA(sm);

    for (int t = 0; t < T; t++) {
        float* cur = sm + (t & 1) * BUF;
        float* nxt = sm + ((t + 1) & 1) * BUF;
        if (t + 1 < T) loadA((t + 1) * 16);
        cpwait0();
        __syncthreads();
        if (t + 1 < T) { issueB((t + 1) * 16, nxt); cpcommit(); }

        const float* Ahb = cur;
        const float* Alb = cur + SA;
        const float* Bhb = cur + 2 * SA;
        const float* Blb = cur + 2 * SA + SB;
#pragma unroll
        for (int k8 = 0; k8 < 2; k8++) {
            wmma::fragment<wmma::matrix_a, 16, 16, 8, wmma::precision::tf32, wmma::row_major> ah[2], al[2];
#pragma unroll
            for (int mi = 0; mi < 2; mi++) {
                wmma::load_matrix_sync(ah[mi], Ahb + (wm * 32 + mi * 16) * 20 + k8 * 8, 20);
                wmma::load_matrix_sync(al[mi], Alb + (wm * 32 + mi * 16) * 20 + k8 * 8, 20);
            }
#pragma unroll
            for (int ni = 0; ni < NF; ni++) {
                wmma::fragment<wmma::matrix_b, 16, 16, 8, wmma::precision::tf32, wmma::row_major> bh, bl;
                wmma::load_matrix_sync(bh, Bhb + (k8 * 8) * SBS + wn * WN + ni * 16, SBS);
                wmma::load_matrix_sync(bl, Blb + (k8 * 8) * SBS + wn * WN + ni * 16, SBS);
#pragma unroll
                for (int mi = 0; mi < 2; mi++) {
                    wmma::mma_sync(acc[mi][ni], ah[mi], bh, acc[mi][ni]);
                    wmma::mma_sync(acc[mi][ni], ah[mi], bl, acc[mi][ni]);
                    wmma::mma_sync(acc[mi][ni], al[mi], bh, acc[mi][ni]);
                }
            }
        }
        if (t + 1 < T) storeA(nxt);
    }

    // epilogue: stage through smem (reused), vectorized write + bias
    __syncthreads();
#pragma unroll
    for (int mi = 0; mi < 2; mi++)
#pragma unroll
        for (int ni = 0; ni < NF; ni++)
            wmma::store_matrix_sync(sm + (wm * 32 + mi * 16) * CTS + wn * WN + ni * 16,
                                    acc[mi][ni], CTS, wmma::mem_row_major);
    __syncthreads();
    constexpr int TOT4 = 128 * BN / 4;
#pragma unroll
    for (int i = 0; i < TOT4 / 256; i++) {
        int idx = tid + i * 256;
        int r = idx / NF4, c4 = idx % NF4;
        float4 v = *(float4*)&sm[r * CTS + c4 * 4];
        float4 bb = *(const float4*)&bias[n0 + c4 * 4];
        v.x += bb.x; v.y += bb.y; v.z += bb.z; v.w += bb.w;
        *(float4*)&C[(size_t)(m0 + r) * LDC + n0 + c4 * 4] = v;
    }
}

// ---------------------------------------------------------------------------
// K2: s partials, fp32 split-K.  s[b,i,j] = sum_n q[b,n,i]*k[b,n,j]
// ---------------------------------------------------------------------------
__global__ __launch_bounds__(256) void s_partial_kernel()
{
    const int sl = blockIdx.x, b = blockIdx.y;
    __shared__ float sq[64][65], sk[64][65];
    const int tid = threadIdx.x;
    const int jj = tid & 63;
    const int ig = tid >> 6;

    float acc[16];
#pragma unroll
    for (int u = 0; u < 16; u++) acc[u] = 0.f;

    for (int c4 = 0; c4 < 4; c4++) {
        int nb = sl * 256 + c4 * 64;
        __syncthreads();
#pragma unroll
        for (int i = 0; i < 16; i++) {
            int idx = tid + i * 256;
            int r = idx >> 6, c = idx & 63;
            const float* row = g_qkv + (size_t)(b * NVOX + nb + r) * QKVN;
            sq[r][c] = row[c];
            sk[r][c] = row[64 + c];
        }
        __syncthreads();
        for (int n = 0; n < 64; n++) {
            float kv = sk[n][jj];
#pragma unroll
            for (int u = 0; u < 16; u++)
                acc[u] += sq[n][ig * 16 + u] * kv;
        }
    }
#pragma unroll
    for (int u = 0; u < 16; u++) {
        int i = ig * 16 + u;
        g_spart[(((b * 64 + sl) * 64) + i) * 64 + jj] = acc[u];
    }
}

// ---------------------------------------------------------------------------
// K3: deterministic reduce of partials + row softmax (axis j)
// ---------------------------------------------------------------------------
__global__ __launch_bounds__(64) void softmax_kernel()
{
    const int i = blockIdx.x, b = blockIdx.y;
    const int j = threadIdx.x;
    float s = 0.f;
    for (int sl = 0; sl < 64; sl++)
        s += g_spart[(((b * 64 + sl) * 64) + i) * 64 + j];

    __shared__ float red[64];
    red[j] = s; __syncthreads();
    for (int o = 32; o > 0; o >>= 1) { if (j < o) red[j] = fmaxf(red[j], red[j + o]); __syncthreads(); }
    float mx = red[0]; __syncthreads();
    float e = expf(s - mx);
    red[j] = e; __syncthreads();
    for (int o = 32; o > 0; o >>= 1) { if (j < o) red[j] += red[j + o]; __syncthreads(); }
    g_beta[((b * 64 + i) * 64) + j] = e / red[0];
}

// ---------------------------------------------------------------------------
// K4: A = v @ beta, stored pre-permuted for the reshape:
//   A_g[b, p, d] = A[b, n, i]  with  p = (i<<8)|(n>>6), d = n&63
// ---------------------------------------------------------------------------
__global__ __launch_bounds__(256) void av_kernel()
{
    const int b = blockIdx.y;
    const int n0 = blockIdx.x * 64;
    __shared__ float sv[64][65];
    __shared__ float sb[64][64];
    const int tid = threadIdx.x;

#pragma unroll
    for (int i = 0; i < 16; i++) {
        int idx = tid + i * 256;
        int r = idx >> 6, c = idx & 63;
        sv[r][c] = g_qkv[(size_t)(b * NVOX + n0 + r) * QKVN + 128 + c];
        sb[r][c] = g_beta[(b * 64 + r) * 64 + c];
    }
    __syncthreads();

    const int lane = tid & 31;
    const int w = tid >> 5;
#pragma unroll
    for (int ii = 0; ii < 8; ii++) {
        int i = w * 8 + ii;
#pragma unroll
        for (int h = 0; h < 2; h++) {
            int n = h * 32 + lane;
            float acc = 0.f;
#pragma unroll
            for (int m = 0; m < 64; m++)
                acc += sv[n][m] * sb[m][i];
            int ng = n0 + n;
            int p = (i << 8) | (ng >> 6);
            int d = ng & 63;
            g_Ag[(size_t)(b * NVOX + p) * C8 + d] = acc;
        }
    }
}

// ---------------------------------------------------------------------------
extern "C" void kernel_launch(void* const* d_in, const int* in_sizes, int n_in,
                              void* d_out, int out_size)
{
    const float* x   = (const float*)d_in[0];
    const float* g1  = (const float*)d_in[1];
    const float* be1 = (const float*)d_in[2];
    const float* m1  = (const float*)d_in[3];
    const float* v1  = (const float*)d_in[4];
    const float* wq  = (const float*)d_in[5];
    const float* bq  = (const float*)d_in[6];
    const float* wk  = (const float*)d_in[7];
    const float* bk  = (const float*)d_in[8];
    const float* wv  = (const float*)d_in[9];
    const float* bv  = (const float*)d_in[10];
    const float* wp  = (const float*)d_in[11];
    const float* bp  = (const float*)d_in[12];
    const float* g2  = (const float*)d_in[13];
    const float* be2 = (const float*)d_in[14];
    const float* m2  = (const float*)d_in[15];
    const float* v2  = (const float*)d_in[16];
    float* out = (float*)d_out;

    // dynamic smem: stage0 needs max(pipeline 92160, Ct 100352) = 100352
    //               stage1 needs max(pipeline 75776,  Ct 67584) = 75776
    static_assert(2 * (2 * 128 * 20 + 2 * 16 * 200) * 4 == 92160, "");
    cudaFuncSetAttribute(gemm3x_pipe<0>, cudaFuncAttributeMaxDynamicSharedMemorySize, 100352);
    cudaFuncSetAttribute(gemm3x_pipe<1>, cudaFuncAttributeMaxDynamicSharedMemorySize, 75776);

    prep_kernel<<<1, 512>>>(g1, be1, m1, v1, wq, bq, wk, bk, wv, bv,
                            wp, bp, g2, be2, m2, v2);

    // QKV GEMM: M = 131072, K = 512, N = 192 (single full-width n tile)
    gemm3x_pipe<0><<<dim3((BB * NVOX) / 128), 256, 100352>>>(x, nullptr);

    // s partials + softmax
    s_partial_kernel<<<dim3(64, BB), 256>>>();
    softmax_kernel<<<dim3(64, BB), 64>>>();

    // A = v @ beta (pre-permuted)
    av_kernel<<<dim3(NVOX / 64, BB), 256>>>();

    // proj GEMM: M = 131072, K = 64, N = 512 (+ folded BN2) -> final output
    gemm3x_pipe<1><<<dim3(CC / 128, (BB * NVOX) / 128), 256, 75776>>>(nullptr, out);
}

// round 4
// speedup vs baseline: 2.0651x; 1.8669x over previous
#include <cuda_runtime.h>
#include <cstdint>

#define BB    8
#define NVOX  16384
#define CC    512
#define C8    64
#define QKVN  192

// ---------------------------------------------------------------------------
// Scratch (device globals)
// ---------------------------------------------------------------------------
__device__ float g_qkv[BB * NVOX * QKVN];
__device__ float g_spart[BB * 64 * 64 * 64];
__device__ float g_beta[BB * 64 * 64];
__device__ float g_Ag[BB * NVOX * C8];

// Weights pre-split to tf32 hi/lo and pre-arranged in mma-fragment layout:
// g_W1f: [t(32)][k8(2)][hl(2)][ntile(24)][lane(32)][2]  (QKV, K=512, N=192)
// g_W2f: [t(4)] [k8(2)][hl(2)][ntile(64)][lane(32)][2]  (proj, K=64,  N=512)
__device__ float g_W1f[32 * 2 * 2 * 24 * 32 * 2];
__device__ float g_b1[QKVN];
__device__ float g_W2f[4 * 2 * 2 * 64 * 32 * 2];
__device__ float g_b2[CC];

// ---------------------------------------------------------------------------
__device__ __forceinline__ float tf32r(float x) {
    unsigned r;
    asm("cvt.rna.tf32.f32 %0, %1;" : "=r"(r) : "f"(x));
    return __uint_as_float(r);
}
__device__ __forceinline__ void cpasync16(void* sdst, const void* g) {
    unsigned s = (unsigned)__cvta_generic_to_shared(sdst);
    asm volatile("cp.async.cg.shared.global [%0], [%1], 16;\n" :: "r"(s), "l"(g));
}
__device__ __forceinline__ void cpcommit() { asm volatile("cp.async.commit_group;\n"); }
__device__ __forceinline__ void cpwait0()  { asm volatile("cp.async.wait_group 0;\n"); }

// D += A(tf32) * B(tf32); m16n8k8, A row-major frag, B col-major frag
__device__ __forceinline__ void mma8(float* d, const uint32_t* a, const uint32_t* b) {
    asm volatile(
        "mma.sync.aligned.m16n8k8.row.col.f32.tf32.tf32.f32 "
        "{%0,%1,%2,%3},{%4,%5,%6,%7},{%8,%9},{%0,%1,%2,%3};"
        : "+f"(d[0]), "+f"(d[1]), "+f"(d[2]), "+f"(d[3])
        : "r"(a[0]), "r"(a[1]), "r"(a[2]), "r"(a[3]), "r"(b[0]), "r"(b[1]));
}

// ---------------------------------------------------------------------------
// K0: prep. Blocks 0..191: one QKV output column n each -> W1f + b1[n].
//          Blocks 192..199: 64 proj columns each -> W2f + b2.
// ---------------------------------------------------------------------------
__global__ __launch_bounds__(256) void prep_kernel(
    const float* __restrict__ g1, const float* __restrict__ be1,
    const float* __restrict__ m1, const float* __restrict__ v1,
    const float* __restrict__ wq, const float* __restrict__ bq,
    const float* __restrict__ wk, const float* __restrict__ bk,
    const float* __restrict__ wv, const float* __restrict__ bv,
    const float* __restrict__ wp, const float* __restrict__ bp,
    const float* __restrict__ g2, const float* __restrict__ be2,
    const float* __restrict__ m2, const float* __restrict__ v2)
{
    __shared__ float sA[CC], sT[CC];
    __shared__ float red[256];
    const int blk = blockIdx.x;
    const int tid = threadIdx.x;

    if (blk < 192) {
        for (int k = tid; k < CC; k += 256) {
            float a = g1[k] * rsqrtf(v1[k] + 1e-3f);
            sA[k] = a;
            sT[k] = be1[k] - m1[k] * a;
        }
        __syncthreads();
        const int n = blk;
        const float* w = (n < 64) ? wq : (n < 128) ? wk : wv;
        const int j = n & 63;
        const int ntile = n >> 3;
        const int lhi = (n & 7) << 2;
        float part = 0.f;
        for (int k = tid; k < CC; k += 256) {
            float wv_ = w[k * 64 + j];
            float val = sA[k] * wv_;
            float hi = tf32r(val);
            float lo = tf32r(val - hi);
            int t = k >> 4, k8 = (k >> 3) & 1, which = (k >> 2) & 1;
            int lane = lhi | (k & 3);
            int base = (((t * 2 + k8) * 2 + 0) * 24 + ntile) * 64 + lane * 2 + which;
            g_W1f[base] = hi;
            g_W1f[base + 24 * 64] = lo;
            part += sT[k] * wv_;
        }
        red[tid] = part; __syncthreads();
        for (int o = 128; o > 0; o >>= 1) { if (tid < o) red[tid] += red[tid + o]; __syncthreads(); }
        if (tid == 0) {
            float b0 = (n < 64) ? bq[j] : (n < 128) ? bk[j] : bv[j];
            g_b1[n] = b0 + red[0];
        }
    } else {
        for (int k = tid; k < CC; k += 256) {
            float a = g2[k] * rsqrtf(v2[k] + 1e-3f);
            sA[k] = a;
            sT[k] = be2[k] - m2[k] * a;
        }
        __syncthreads();
        const int n0 = (blk - 192) * 64;
        for (int idx = tid; idx < 64 * 64; idx += 256) {
            int n = n0 + (idx >> 6), k = idx & 63;
            float val = wp[k * CC + n] * sA[n];
            float hi = tf32r(val);
            float lo = tf32r(val - hi);
            int t = k >> 4, k8 = (k >> 3) & 1, which = (k >> 2) & 1;
            int lane = ((n & 7) << 2) | (k & 3);
            int ntile = n >> 3;
            int base = (((t * 2 + k8) * 2 + 0) * 64 + ntile) * 64 + lane * 2 + which;
            g_W2f[base] = hi;
            g_W2f[base + 64 * 64] = lo;
        }
        if (tid < 64) {
            int n = n0 + tid;
            g_b2[n] = bp[n] * sA[n] + sT[n];
        }
    }
}

// ---------------------------------------------------------------------------
// K1: QKV GEMM tf32x3, manual m16n8k8. CTA: 128m x 192n, K=512 (32 chunks).
// 512 threads = 16 warps (4m x 4n). Warp tile 32m x 48n.
// smem: Abuf[2] 4096 floats each (frag layout), Bbuf[2] 6144 floats each.
// ---------------------------------------------------------------------------
#define SMEM_QKV (2 * (4096 + 6144) * 4)   // 81920 B

__global__ __launch_bounds__(512, 1) void gemm_qkv(const float* __restrict__ X)
{
    extern __shared__ float sm[];
    float* Ab0 = sm;
    float* Ab1 = sm + 4096;
    float* Bb0 = sm + 8192;
    float* Bb1 = sm + 8192 + 6144;

    const int tid = threadIdx.x;
    const int wid = tid >> 5, lane = tid & 31;
    const int wm = wid & 3, wn = wid >> 2;
    const int m0 = blockIdx.x * 128;

    const int ar = tid >> 2;            // 0..127 (row)
    const int ac = (tid & 3) * 4;       // 0,4,8,12 (col within 16-chunk)
    const int amtile = ar >> 4, arr = ar & 15;

    float acc[2][6][4];
#pragma unroll
    for (int i = 0; i < 2; i++)
#pragma unroll
        for (int j = 0; j < 6; j++)
#pragma unroll
            for (int q = 0; q < 4; q++) acc[i][j][q] = 0.f;

    float4 areg;

    auto ldgA = [&](int t) {
        areg = *(const float4*)(X + (size_t)(m0 + ar) * CC + t * 16 + ac);
    };
    auto stsA = [&](float* Ab) {
        float vv[4] = {areg.x, areg.y, areg.z, areg.w};
#pragma unroll
        for (int q = 0; q < 4; q++) {
            int c = ac + q;
            int k8 = c >> 3, cc = c & 7;
            int ln = ((arr & 7) << 2) | (cc & 3);
            int j = (arr >> 3) | (((cc >> 2) & 1) << 1);
            float hi = tf32r(vv[q]);
            Ab[((amtile * 2 + k8) * 2 + 0) * 128 + ln * 4 + j] = hi;
            Ab[((amtile * 2 + k8) * 2 + 1) * 128 + ln * 4 + j] = tf32r(vv[q] - hi);
        }
    };
    auto cpB = [&](int t, float* Bb) {
        const float* src = g_W1f + t * 6144;
#pragma unroll
        for (int i = 0; i < 3; i++) {
            int v = tid + i * 512;
            cpasync16(&Bb[v * 4], src + v * 4);
        }
        cpcommit();
    };
    auto compute = [&](const float* Ab, const float* Bb) {
#pragma unroll
        for (int k8 = 0; k8 < 2; k8++) {
            uint32_t af[2][2][4];
#pragma unroll
            for (int mi = 0; mi < 2; mi++)
#pragma unroll
                for (int hl = 0; hl < 2; hl++) {
                    float4 t4 = *(const float4*)&Ab[(((wm * 2 + mi) * 2 + k8) * 2 + hl) * 128 + lane * 4];
                    af[mi][hl][0] = __float_as_uint(t4.x);
                    af[mi][hl][1] = __float_as_uint(t4.y);
                    af[mi][hl][2] = __float_as_uint(t4.z);
                    af[mi][hl][3] = __float_as_uint(t4.w);
                }
#pragma unroll
            for (int ni = 0; ni < 6; ni++) {
                int nt = wn * 6 + ni;
                uint32_t bh[2], bl[2];
                {
                    float2 t2 = *(const float2*)&Bb[((k8 * 2 + 0) * 24 + nt) * 64 + lane * 2];
                    bh[0] = __float_as_uint(t2.x); bh[1] = __float_as_uint(t2.y);
                    float2 u2 = *(const float2*)&Bb[((k8 * 2 + 1) * 24 + nt) * 64 + lane * 2];
                    bl[0] = __float_as_uint(u2.x); bl[1] = __float_as_uint(u2.y);
                }
#pragma unroll
                for (int mi = 0; mi < 2; mi++) {
                    mma8(acc[mi][ni], af[mi][0], bh);
                    mma8(acc[mi][ni], af[mi][0], bl);
                    mma8(acc[mi][ni], af[mi][1], bh);
                }
            }
        }
    };

    ldgA(0);
    cpB(0, Bb0);
    stsA(Ab0);

    for (int t = 0; t < 32; t++) {
        float* Ac = (t & 1) ? Ab1 : Ab0;
        float* Bc = (t & 1) ? Bb1 : Bb0;
        float* An = (t & 1) ? Ab0 : Ab1;
        float* Bn = (t & 1) ? Bb0 : Bb1;
        if (t + 1 < 32) ldgA(t + 1);
        cpwait0();
        __syncthreads();
        if (t + 1 < 32) cpB(t + 1, Bn);
        compute(Ac, Bc);
        if (t + 1 < 32) stsA(An);
    }

    // Epilogue: bias + direct STG.64 (32B sectors per 4-lane group)
    const int gid = lane >> 2, tg = lane & 3;
#pragma unroll
    for (int mi = 0; mi < 2; mi++) {
        int r0 = m0 + wm * 32 + mi * 16 + gid;
#pragma unroll
        for (int ni = 0; ni < 6; ni++) {
            int col = wn * 48 + ni * 8 + tg * 2;
            float b0 = g_b1[col], b1 = g_b1[col + 1];
            float2 v0 = make_float2(acc[mi][ni][0] + b0, acc[mi][ni][1] + b1);
            float2 v1 = make_float2(acc[mi][ni][2] + b0, acc[mi][ni][3] + b1);
            *(float2*)&g_qkv[(size_t)r0 * QKVN + col] = v0;
            *(float2*)&g_qkv[(size_t)(r0 + 8) * QKVN + col] = v1;
        }
    }
}

// ---------------------------------------------------------------------------
// K5: proj GEMM tf32x3. CTA: 128m x 256n (nh half), K=64 (4 chunks).
// 512 threads, warps 4m x 4n, warp tile 32m x 64n (ni=8).
// ---------------------------------------------------------------------------
#define SMEM_PROJ (2 * (4096 + 8192) * 4)  // 98304 B

__global__ __launch_bounds__(512, 1) void gemm_proj(float* __restrict__ Out)
{
    extern __shared__ float sm[];
    float* Ab0 = sm;
    float* Ab1 = sm + 4096;
    float* Bb0 = sm + 8192;
    float* Bb1 = sm + 8192 + 8192;

    const int tid = threadIdx.x;
    const int wid = tid >> 5, lane = tid & 31;
    const int wm = wid & 3, wn = wid >> 2;
    const int nh = blockIdx.x;
    const int m0 = blockIdx.y * 128;

    const int ar = tid >> 2;
    const int ac = (tid & 3) * 4;
    const int amtile = ar >> 4, arr = ar & 15;

    float acc[2][8][4];
#pragma unroll
    for (int i = 0; i < 2; i++)
#pragma unroll
        for (int j = 0; j < 8; j++)
#pragma unroll
            for (int q = 0; q < 4; q++) acc[i][j][q] = 0.f;

    float4 areg;

    auto ldgA = [&](int t) {
        areg = *(const float4*)(g_Ag + (size_t)(m0 + ar) * C8 + t * 16 + ac);
    };
    auto stsA = [&](float* Ab) {
        float vv[4] = {areg.x, areg.y, areg.z, areg.w};
#pragma unroll
        for (int q = 0; q < 4; q++) {
            int c = ac + q;
            int k8 = c >> 3, cc = c & 7;
            int ln = ((arr & 7) << 2) | (cc & 3);
            int j = (arr >> 3) | (((cc >> 2) & 1) << 1);
            float hi = tf32r(vv[q]);
            Ab[((amtile * 2 + k8) * 2 + 0) * 128 + ln * 4 + j] = hi;
            Ab[((amtile * 2 + k8) * 2 + 1) * 128 + ln * 4 + j] = tf32r(vv[q] - hi);
        }
    };
    auto cpB = [&](int t, float* Bb) {
#pragma unroll
        for (int s = 0; s < 4; s++) {   // s = k8*2 + hl
            const float* src = g_W2f + ((size_t)t * 4 + s) * 4096 + nh * 2048 + tid * 4;
            cpasync16(&Bb[s * 2048 + tid * 4], src);
        }
        cpcommit();
    };
    auto compute = [&](const float* Ab, const float* Bb) {
#pragma unroll
        for (int k8 = 0; k8 < 2; k8++) {
            uint32_t af[2][2][4];
#pragma unroll
            for (int mi = 0; mi < 2; mi++)
#pragma unroll
                for (int hl = 0; hl < 2; hl++) {
                    float4 t4 = *(const float4*)&Ab[(((wm * 2 + mi) * 2 + k8) * 2 + hl) * 128 + lane * 4];
                    af[mi][hl][0] = __float_as_uint(t4.x);
                    af[mi][hl][1] = __float_as_uint(t4.y);
                    af[mi][hl][2] = __float_as_uint(t4.z);
                    af[mi][hl][3] = __float_as_uint(t4.w);
                }
#pragma unroll
            for (int ni = 0; ni < 8; ni++) {
                int nt = wn * 8 + ni;
                uint32_t bh[2], bl[2];
                {
                    float2 t2 = *(const float2*)&Bb[(k8 * 2 + 0) * 2048 + nt * 64 + lane * 2];
                    bh[0] = __float_as_uint(t2.x); bh[1] = __float_as_uint(t2.y);
                    float2 u2 = *(const float2*)&Bb[(k8 * 2 + 1) * 2048 + nt * 64 + lane * 2];
                    bl[0] = __float_as_uint(u2.x); bl[1] = __float_as_uint(u2.y);
                }
#pragma unroll
                for (int mi = 0; mi < 2; mi++) {
                    mma8(acc[mi][ni], af[mi][0], bh);
                    mma8(acc[mi][ni], af[mi][0], bl);
                    mma8(acc[mi][ni], af[mi][1], bh);
                }
            }
        }
    };

    ldgA(0);
    cpB(0, Bb0);
    stsA(Ab0);

    for (int t = 0; t < 4; t++) {
        float* Ac = (t & 1) ? Ab1 : Ab0;
        float* Bc = (t & 1) ? Bb1 : Bb0;
        float* An = (t & 1) ? Ab0 : Ab1;
        float* Bn = (t & 1) ? Bb0 : Bb1;
        if (t + 1 < 4) ldgA(t + 1);
        cpwait0();
        __syncthreads();
        if (t + 1 < 4) cpB(t + 1, Bn);
        compute(Ac, Bc);
        if (t + 1 < 4) stsA(An);
    }

    const int gid = lane >> 2, tg = lane & 3;
#pragma unroll
    for (int mi = 0; mi < 2; mi++) {
        int r0 = m0 + wm * 32 + mi * 16 + gid;
#pragma unroll
        for (int ni = 0; ni < 8; ni++) {
            int col = nh * 256 + wn * 64 + ni * 8 + tg * 2;
            float b0 = g_b2[col], b1 = g_b2[col + 1];
            float2 v0 = make_float2(acc[mi][ni][0] + b0, acc[mi][ni][1] + b1);
            float2 v1 = make_float2(acc[mi][ni][2] + b0, acc[mi][ni][3] + b1);
            *(float2*)&Out[(size_t)r0 * CC + col] = v0;
            *(float2*)&Out[(size_t)(r0 + 8) * CC + col] = v1;
        }
    }
}

// ---------------------------------------------------------------------------
// K2: s partials, fp32 split-K.  s[b,i,j] = sum_n q[b,n,i]*k[b,n,j]
// ---------------------------------------------------------------------------
__global__ __launch_bounds__(256) void s_partial_kernel()
{
    const int sl = blockIdx.x, b = blockIdx.y;
    __shared__ float sq[64][68], sk[64][68];
    const int tid = threadIdx.x;
    const int jj = tid & 63;
    const int ig = tid >> 6;

    float acc[16];
#pragma unroll
    for (int u = 0; u < 16; u++) acc[u] = 0.f;

    for (int c4 = 0; c4 < 4; c4++) {
        int nb = sl * 256 + c4 * 64;
        __syncthreads();
#pragma unroll
        for (int i = 0; i < 16; i++) {
            int idx = tid + i * 256;
            int r = idx >> 6, c = idx & 63;
            const float* row = g_qkv + (size_t)(b * NVOX + nb + r) * QKVN;
            sq[r][c] = row[c];
            sk[r][c] = row[64 + c];
        }
        __syncthreads();
        for (int n = 0; n < 64; n++) {
            float kv = sk[n][jj];
            const float4* qp = (const float4*)&sq[n][ig * 16];
            float4 q0 = qp[0], q1 = qp[1], q2 = qp[2], q3 = qp[3];
            acc[0]  += q0.x * kv; acc[1]  += q0.y * kv; acc[2]  += q0.z * kv; acc[3]  += q0.w * kv;
            acc[4]  += q1.x * kv; acc[5]  += q1.y * kv; acc[6]  += q1.z * kv; acc[7]  += q1.w * kv;
            acc[8]  += q2.x * kv; acc[9]  += q2.y * kv; acc[10] += q2.z * kv; acc[11] += q2.w * kv;
            acc[12] += q3.x * kv; acc[13] += q3.y * kv; acc[14] += q3.z * kv; acc[15] += q3.w * kv;
        }
    }
#pragma unroll
    for (int u = 0; u < 16; u++) {
        int i = ig * 16 + u;
        g_spart[(((b * 64 + sl) * 64) + i) * 64 + jj] = acc[u];
    }
}

// ---------------------------------------------------------------------------
// K3: deterministic reduce + row softmax
// ---------------------------------------------------------------------------
__global__ __launch_bounds__(64) void softmax_kernel()
{
    const int i = blockIdx.x, b = blockIdx.y;
    const int j = threadIdx.x;
    float s = 0.f;
    for (int sl = 0; sl < 64; sl++)
        s += g_spart[(((b * 64 + sl) * 64) + i) * 64 + j];

    __shared__ float red[64];
    red[j] = s; __syncthreads();
    for (int o = 32; o > 0; o >>= 1) { if (j < o) red[j] = fmaxf(red[j], red[j + o]); __syncthreads(); }
    float mx = red[0]; __syncthreads();
    float e = expf(s - mx);
    red[j] = e; __syncthreads();
    for (int o = 32; o > 0; o >>= 1) { if (j < o) red[j] += red[j + o]; __syncthreads(); }
    g_beta[((b * 64 + i) * 64) + j] = e / red[0];
}

// ---------------------------------------------------------------------------
// K4: A = v @ beta, stored pre-permuted for the reshape
// ---------------------------------------------------------------------------
__global__ __launch_bounds__(256) void av_kernel()
{
    const int b = blockIdx.y;
    const int n0 = blockIdx.x * 64;
    __shared__ float sv[64][65];
    __shared__ float sb_[64][64];
    const int tid = threadIdx.x;

#pragma unroll
    for (int i = 0; i < 16; i++) {
        int idx = tid + i * 256;
        int r = idx >> 6, c = idx & 63;
        sv[r][c] = g_qkv[(size_t)(b * NVOX + n0 + r) * QKVN + 128 + c];
        sb_[r][c] = g_beta[(b * 64 + r) * 64 + c];
    }
    __syncthreads();

    const int lane = tid & 31;
    const int w = tid >> 5;
#pragma unroll
    for (int ii = 0; ii < 8; ii++) {
        int i = w * 8 + ii;
#pragma unroll
        for (int h = 0; h < 2; h++) {
            int n = h * 32 + lane;
            float acc = 0.f;
#pragma unroll
            for (int m = 0; m < 64; m++)
                acc += sv[n][m] * sb_[m][i];
            int ng = n0 + n;
            int p = (i << 8) | (ng >> 6);
            int d = ng & 63;
            g_Ag[(size_t)(b * NVOX + p) * C8 + d] = acc;
        }
    }
}

// ---------------------------------------------------------------------------
extern "C" void kernel_launch(void* const* d_in, const int* in_sizes, int n_in,
                              void* d_out, int out_size)
{
    const float* x   = (const float*)d_in[0];
    const float* g1  = (const float*)d_in[1];
    const float* be1 = (const float*)d_in[2];
    const float* m1  = (const float*)d_in[3];
    const float* v1  = (const float*)d_in[4];
    const float* wq  = (const float*)d_in[5];
    const float* bq  = (const float*)d_in[6];
    const float* wk  = (const float*)d_in[7];
    const float* bk  = (const float*)d_in[8];
    const float* wv  = (const float*)d_in[9];
    const float* bv  = (const float*)d_in[10];
    const float* wp  = (const float*)d_in[11];
    const float* bp  = (const float*)d_in[12];
    const float* g2  = (const float*)d_in[13];
    const float* be2 = (const float*)d_in[14];
    const float* m2  = (const float*)d_in[15];
    const float* v2  = (const float*)d_in[16];
    float* out = (float*)d_out;

    cudaFuncSetAttribute(gemm_qkv,  cudaFuncAttributeMaxDynamicSharedMemorySize, SMEM_QKV);
    cudaFuncSetAttribute(gemm_proj, cudaFuncAttributeMaxDynamicSharedMemorySize, SMEM_PROJ);

    prep_kernel<<<200, 256>>>(g1, be1, m1, v1, wq, bq, wk, bk, wv, bv,
                              wp, bp, g2, be2, m2, v2);

    gemm_qkv<<<(BB * NVOX) / 128, 512, SMEM_QKV>>>(x);

    s_partial_kernel<<<dim3(64, BB), 256>>>();
    softmax_kernel<<<dim3(64, BB), 64>>>();
    av_kernel<<<dim3(NVOX / 64, BB), 256>>>();

    gemm_proj<<<dim3(2, (BB * NVOX) / 128), 512, SMEM_PROJ>>>(out);
}

// round 5
// speedup vs baseline: 2.7052x; 1.3100x over previous
#include <cuda_runtime.h>
#include <cuda_fp16.h>
#include <cstdint>

#define BB    8
#define NVOX  16384
#define CC    512
#define C8    64
#define QKVN  192

// ---------------------------------------------------------------------------
// Scratch (device globals)
// ---------------------------------------------------------------------------
__device__ float g_qkv[BB * NVOX * QKVN];
__device__ float g_spart[BB * 64 * 64 * 64];
__device__ float g_beta[BB * 64 * 64];
__device__ float g_Ag[BB * NVOX * C8];

// Weights pre-split to fp16 hi/lo in exact m16n8k16 B-fragment layout:
// g_W1f: [t(32)][hl(2)][ntile(24)][lane(32)][reg(2)][half(2)]   (K=512, N=192)
// g_W2f: [t(4)] [hl(2)][ntile(64)][lane(32)][reg(2)][half(2)]   (K=64,  N=512)
__device__ __half g_W1f[512 * 192 * 2];
__device__ float  g_b1[QKVN];
__device__ __half g_W2f[64 * 512 * 2];
__device__ float  g_b2[CC];

// ---------------------------------------------------------------------------
__device__ __forceinline__ void cpasync16(void* sdst, const void* g) {
    unsigned s = (unsigned)__cvta_generic_to_shared(sdst);
    asm volatile("cp.async.cg.shared.global [%0], [%1], 16;\n" :: "r"(s), "l"(g));
}
__device__ __forceinline__ void cpcommit() { asm volatile("cp.async.commit_group;\n"); }
__device__ __forceinline__ void cpwait0()  { asm volatile("cp.async.wait_group 0;\n"); }

__device__ __forceinline__ void ldmat4(uint32_t* r, const void* p) {
    uint32_t a = (uint32_t)__cvta_generic_to_shared(p);
    asm volatile("ldmatrix.sync.aligned.m8n8.x4.shared.b16 {%0,%1,%2,%3}, [%4];"
        : "=r"(r[0]), "=r"(r[1]), "=r"(r[2]), "=r"(r[3]) : "r"(a));
}

// D += A(f16) * B(f16), fp32 accum; m16n8k16
__device__ __forceinline__ void mma16(float* d, const uint32_t* a, const uint32_t* b) {
    asm volatile(
        "mma.sync.aligned.m16n8k16.row.col.f32.f16.f16.f32 "
        "{%0,%1,%2,%3},{%4,%5,%6,%7},{%8,%9},{%0,%1,%2,%3};"
        : "+f"(d[0]), "+f"(d[1]), "+f"(d[2]), "+f"(d[3])
        : "r"(a[0]), "r"(a[1]), "r"(a[2]), "r"(a[3]), "r"(b[0]), "r"(b[1]));
}

// fragment index helpers (B operand k16n8): k within 16-chunk, n within tile-8
__device__ __forceinline__ int bfrag_idx(int t, int hl, int ntile, int NT, int k, int n) {
    int lane = ((n & 7) << 2) | ((k & 7) >> 1);
    int reg = (k >> 3) & 1;
    int halfsel = k & 1;
    return ((((t * 2 + hl) * NT + ntile) * 32 + lane) * 2 + reg) * 2 + halfsel;
}

// ---------------------------------------------------------------------------
// K0: prep. Blocks 0..191: QKV col n -> g_W1f frags + b1. 192..199: proj.
// ---------------------------------------------------------------------------
__global__ __launch_bounds__(256) void prep_kernel(
    const float* __restrict__ g1, const float* __restrict__ be1,
    const float* __restrict__ m1, const float* __restrict__ v1,
    const float* __restrict__ wq, const float* __restrict__ bq,
    const float* __restrict__ wk, const float* __restrict__ bk,
    const float* __restrict__ wv, const float* __restrict__ bv,
    const float* __restrict__ wp, const float* __restrict__ bp,
    const float* __restrict__ g2, const float* __restrict__ be2,
    const float* __restrict__ m2, const float* __restrict__ v2)
{
    __shared__ float sA[CC], sT[CC];
    __shared__ float red[256];
    const int blk = blockIdx.x;
    const int tid = threadIdx.x;

    if (blk < 192) {
        for (int k = tid; k < CC; k += 256) {
            float a = g1[k] * rsqrtf(v1[k] + 1e-3f);
            sA[k] = a;
            sT[k] = be1[k] - m1[k] * a;
        }
        __syncthreads();
        const int n = blk;
        const float* w = (n < 64) ? wq : (n < 128) ? wk : wv;
        const int j = n & 63;
        const int ntile = n >> 3;
        float part = 0.f;
        for (int k = tid; k < CC; k += 256) {
            float wv_ = w[k * 64 + j];
            float val = sA[k] * wv_;
            __half hi = __float2half(val);
            __half lo = __float2half(val - __half2float(hi));
            int t = k >> 4;
            g_W1f[bfrag_idx(t, 0, ntile, 24, k & 15, n & 7)] = hi;
            g_W1f[bfrag_idx(t, 1, ntile, 24, k & 15, n & 7)] = lo;
            part += sT[k] * wv_;
        }
        red[tid] = part; __syncthreads();
        for (int o = 128; o > 0; o >>= 1) { if (tid < o) red[tid] += red[tid + o]; __syncthreads(); }
        if (tid == 0) {
            float b0 = (n < 64) ? bq[j] : (n < 128) ? bk[j] : bv[j];
            g_b1[n] = b0 + red[0];
        }
    } else {
        for (int k = tid; k < CC; k += 256) {
            float a = g2[k] * rsqrtf(v2[k] + 1e-3f);
            sA[k] = a;
            sT[k] = be2[k] - m2[k] * a;
        }
        __syncthreads();
        const int n0 = (blk - 192) * 64;
        for (int idx = tid; idx < 64 * 64; idx += 256) {
            int n = n0 + (idx >> 6), k = idx & 63;
            float val = wp[k * CC + n] * sA[n];
            __half hi = __float2half(val);
            __half lo = __float2half(val - __half2float(hi));
            int t = k >> 4;
            g_W2f[bfrag_idx(t, 0, n >> 3, 64, k & 15, n & 7)] = hi;
            g_W2f[bfrag_idx(t, 1, n >> 3, 64, k & 15, n & 7)] = lo;
        }
        if (tid < 64) {
            int n = n0 + tid;
            g_b2[n] = bp[n] * sA[n] + sT[n];
        }
    }
}

// ---------------------------------------------------------------------------
// K1: QKV GEMM fp16x3, m16n8k16. CTA: 128m x 192n, K=512 (32 chunks of 16).
// 512 threads = 16 warps (4m x 4n). Warp tile 32m x 48n.
// A smem per buf: [hl(2)][row(128)][24 halfs (16+8 pad, ldmatrix-friendly)]
// B smem per buf: fragment layout, 6144 halfs.
// ---------------------------------------------------------------------------
#define ABUF 6144   // halfs per A buffer
#define SMEM_QKV ((2 * 6144 + 2 * 6144) * 2)   // 49152 B

__global__ __launch_bounds__(512, 1) void gemm_qkv(const float* __restrict__ X)
{
    extern __shared__ __half smh[];
    __half* Ab0 = smh;
    __half* Ab1 = smh + ABUF;
    __half* Bb0 = smh + 2 * ABUF;
    __half* Bb1 = smh + 3 * ABUF;

    const int tid = threadIdx.x;
    const int wid = tid >> 5, lane = tid & 31;
    const int wm = wid & 3, wn = wid >> 2;
    const int m0 = blockIdx.x * 128;

    const int ar = tid >> 2;            // row 0..127
    const int ac = (tid & 3) * 4;       // col 0,4,8,12

    float acc[2][6][4];
#pragma unroll
    for (int i = 0; i < 2; i++)
#pragma unroll
        for (int j = 0; j < 6; j++)
#pragma unroll
            for (int q = 0; q < 4; q++) acc[i][j][q] = 0.f;

    float4 areg;

    auto ldgA = [&](int t) {
        areg = *(const float4*)(X + (size_t)(m0 + ar) * CC + t * 16 + ac);
    };
    auto stsA = [&](__half* Ab) {
        float vv[4] = {areg.x, areg.y, areg.z, areg.w};
        __half h[4], l[4];
#pragma unroll
        for (int q = 0; q < 4; q++) {
            h[q] = __float2half(vv[q]);
            l[q] = __float2half(vv[q] - __half2float(h[q]));
        }
        *(uint2*)&Ab[ar * 24 + ac] = *(uint2*)h;
        *(uint2*)&Ab[(128 + ar) * 24 + ac] = *(uint2*)l;
    };
    auto cpB = [&](int t, __half* Bb) {
        const __half* src = g_W1f + (size_t)t * 6144;
        cpasync16(&Bb[tid * 8], src + tid * 8);
        if (tid < 256) cpasync16(&Bb[(512 + tid) * 8], src + (512 + tid) * 8);
        cpcommit();
    };
    auto compute = [&](const __half* Ab, const __half* Bb) {
        uint32_t af[2][2][4];
#pragma unroll
        for (int mi = 0; mi < 2; mi++)
#pragma unroll
            for (int hl = 0; hl < 2; hl++)
                ldmat4(af[mi][hl],
                       &Ab[(hl * 128 + wm * 32 + mi * 16 + (lane & 15)) * 24 + (lane >> 4) * 8]);
#pragma unroll
        for (int ni = 0; ni < 6; ni++) {
            int nt = wn * 6 + ni;
            uint32_t bh[2], bl[2];
            *(uint2*)bh = *(const uint2*)&Bb[((0 * 24 + nt) * 32 + lane) * 4];
            *(uint2*)bl = *(const uint2*)&Bb[((1 * 24 + nt) * 32 + lane) * 4];
#pragma unroll
            for (int mi = 0; mi < 2; mi++) {
                mma16(acc[mi][ni], af[mi][0], bh);
                mma16(acc[mi][ni], af[mi][0], bl);
                mma16(acc[mi][ni], af[mi][1], bh);
            }
        }
    };

    ldgA(0);
    cpB(0, Bb0);
    stsA(Ab0);

    for (int t = 0; t < 32; t++) {
        __half* Ac = (t & 1) ? Ab1 : Ab0;
        __half* Bc = (t & 1) ? Bb1 : Bb0;
        __half* An = (t & 1) ? Ab0 : Ab1;
        __half* Bn = (t & 1) ? Bb0 : Bb1;
        if (t + 1 < 32) ldgA(t + 1);
        cpwait0();
        __syncthreads();
        if (t + 1 < 32) cpB(t + 1, Bn);
        compute(Ac, Bc);
        if (t + 1 < 32) stsA(An);
    }

    const int gid = lane >> 2, tg = lane & 3;
#pragma unroll
    for (int mi = 0; mi < 2; mi++) {
        int r0 = m0 + wm * 32 + mi * 16 + gid;
#pragma unroll
        for (int ni = 0; ni < 6; ni++) {
            int col = wn * 48 + ni * 8 + tg * 2;
            float b0 = g_b1[col], b1 = g_b1[col + 1];
            float2 v0 = make_float2(acc[mi][ni][0] + b0, acc[mi][ni][1] + b1);
            float2 v1 = make_float2(acc[mi][ni][2] + b0, acc[mi][ni][3] + b1);
            *(float2*)&g_qkv[(size_t)r0 * QKVN + col] = v0;
            *(float2*)&g_qkv[(size_t)(r0 + 8) * QKVN + col] = v1;
        }
    }
}

// ---------------------------------------------------------------------------
// K5: proj GEMM fp16x3. CTA: 128m x 256n (nh half), K=64 (4 chunks of 16).
// 512 threads, 16 warps (4m x 4n), warp tile 32m x 64n.
// B smem per buf: [hl(2)][ntile_local(32)][lane][reg][half] = 8192 halfs.
// ---------------------------------------------------------------------------
#define SMEM_PROJ ((2 * 6144 + 2 * 8192) * 2)  // 57344 B

__global__ __launch_bounds__(512, 1) void gemm_proj(float* __restrict__ Out)
{
    extern __shared__ __half smh[];
    __half* Ab0 = smh;
    __half* Ab1 = smh + ABUF;
    __half* Bb0 = smh + 2 * ABUF;
    __half* Bb1 = smh + 2 * ABUF + 8192;

    const int tid = threadIdx.x;
    const int wid = tid >> 5, lane = tid & 31;
    const int wm = wid & 3, wn = wid >> 2;
    const int nh = blockIdx.x;
    const int m0 = blockIdx.y * 128;

    const int ar = tid >> 2;
    const int ac = (tid & 3) * 4;

    float acc[2][8][4];
#pragma unroll
    for (int i = 0; i < 2; i++)
#pragma unroll
        for (int j = 0; j < 8; j++)
#pragma unroll
            for (int q = 0; q < 4; q++) acc[i][j][q] = 0.f;

    float4 areg;

    auto ldgA = [&](int t) {
        areg = *(const float4*)(g_Ag + (size_t)(m0 + ar) * C8 + t * 16 + ac);
    };
    auto stsA = [&](__half* Ab) {
        float vv[4] = {areg.x, areg.y, areg.z, areg.w};
        __half h[4], l[4];
#pragma unroll
        for (int q = 0; q < 4; q++) {
            h[q] = __float2half(vv[q]);
            l[q] = __float2half(vv[q] - __half2float(h[q]));
        }
        *(uint2*)&Ab[ar * 24 + ac] = *(uint2*)h;
        *(uint2*)&Ab[(128 + ar) * 24 + ac] = *(uint2*)l;
    };
    auto cpB = [&](int t, __half* Bb) {
#pragma unroll
        for (int hl = 0; hl < 2; hl++) {
            const __half* src = g_W2f + ((size_t)(t * 2 + hl) * 64 + nh * 32) * 128;
            cpasync16(&Bb[hl * 4096 + tid * 8], src + tid * 8);
        }
        cpcommit();
    };
    auto compute = [&](const __half* Ab, const __half* Bb) {
        uint32_t af[2][2][4];
#pragma unroll
        for (int mi = 0; mi < 2; mi++)
#pragma unroll
            for (int hl = 0; hl < 2; hl++)
                ldmat4(af[mi][hl],
                       &Ab[(hl * 128 + wm * 32 + mi * 16 + (lane & 15)) * 24 + (lane >> 4) * 8]);
#pragma unroll
        for (int ni = 0; ni < 8; ni++) {
            int ntl = wn * 8 + ni;
            uint32_t bh[2], bl[2];
            *(uint2*)bh = *(const uint2*)&Bb[(ntl * 32 + lane) * 4];
            *(uint2*)bl = *(const uint2*)&Bb[4096 + (ntl * 32 + lane) * 4];
#pragma unroll
            for (int mi = 0; mi < 2; mi++) {
                mma16(acc[mi][ni], af[mi][0], bh);
                mma16(acc[mi][ni], af[mi][0], bl);
                mma16(acc[mi][ni], af[mi][1], bh);
            }
        }
    };

    ldgA(0);
    cpB(0, Bb0);
    stsA(Ab0);

    for (int t = 0; t < 4; t++) {
        __half* Ac = (t & 1) ? Ab1 : Ab0;
        __half* Bc = (t & 1) ? Bb1 : Bb0;
        __half* An = (t & 1) ? Ab0 : Ab1;
        __half* Bn = (t & 1) ? Bb0 : Bb1;
        if (t + 1 < 4) ldgA(t + 1);
        cpwait0();
        __syncthreads();
        if (t + 1 < 4) cpB(t + 1, Bn);
        compute(Ac, Bc);
        if (t + 1 < 4) stsA(An);
    }

    const int gid = lane >> 2, tg = lane & 3;
#pragma unroll
    for (int mi = 0; mi < 2; mi++) {
        int r0 = m0 + wm * 32 + mi * 16 + gid;
#pragma unroll
        for (int ni = 0; ni < 8; ni++) {
            int col = nh * 256 + wn * 64 + ni * 8 + tg * 2;
            float b0 = g_b2[col], b1 = g_b2[col + 1];
            float2 v0 = make_float2(acc[mi][ni][0] + b0, acc[mi][ni][1] + b1);
            float2 v1 = make_float2(acc[mi][ni][2] + b0, acc[mi][ni][3] + b1);
            *(float2*)&Out[(size_t)r0 * CC + col] = v0;
            *(float2*)&Out[(size_t)(r0 + 8) * CC + col] = v1;
        }
    }
}

// ---------------------------------------------------------------------------
// K2: s partials, fp32 split-K.  s[b,i,j] = sum_n q[b,n,i]*k[b,n,j]
// ---------------------------------------------------------------------------
__global__ __launch_bounds__(256) void s_partial_kernel()
{
    const int sl = blockIdx.x, b = blockIdx.y;
    __shared__ float sq[64][68], sk[64][68];
    const int tid = threadIdx.x;
    const int jj = tid & 63;
    const int ig = tid >> 6;

    float acc[16];
#pragma unroll
    for (int u = 0; u < 16; u++) acc[u] = 0.f;

    for (int c4 = 0; c4 < 4; c4++) {
        int nb = sl * 256 + c4 * 64;
        __syncthreads();
#pragma unroll
        for (int i = 0; i < 16; i++) {
            int idx = tid + i * 256;
            int r = idx >> 6, c = idx & 63;
            const float* row = g_qkv + (size_t)(b * NVOX + nb + r) * QKVN;
            sq[r][c] = row[c];
            sk[r][c] = row[64 + c];
        }
        __syncthreads();
        for (int n = 0; n < 64; n++) {
            float kv = sk[n][jj];
            const float4* qp = (const float4*)&sq[n][ig * 16];
            float4 q0 = qp[0], q1 = qp[1], q2 = qp[2], q3 = qp[3];
            acc[0]  += q0.x * kv; acc[1]  += q0.y * kv; acc[2]  += q0.z * kv; acc[3]  += q0.w * kv;
            acc[4]  += q1.x * kv; acc[5]  += q1.y * kv; acc[6]  += q1.z * kv; acc[7]  += q1.w * kv;
            acc[8]  += q2.x * kv; acc[9]  += q2.y * kv; acc[10] += q2.z * kv; acc[11] += q2.w * kv;
            acc[12] += q3.x * kv; acc[13] += q3.y * kv; acc[14] += q3.z * kv; acc[15] += q3.w * kv;
        }
    }
#pragma unroll
    for (int u = 0; u < 16; u++) {
        int i = ig * 16 + u;
        g_spart[(((b * 64 + sl) * 64) + i) * 64 + jj] = acc[u];
    }
}

// ---------------------------------------------------------------------------
// K3: deterministic reduce + row softmax
// ---------------------------------------------------------------------------
__global__ __launch_bounds__(64) void softmax_kernel()
{
    const int i = blockIdx.x, b = blockIdx.y;
    const int j = threadIdx.x;
    float s = 0.f;
    for (int sl = 0; sl < 64; sl++)
        s += g_spart[(((b * 64 + sl) * 64) + i) * 64 + j];

    __shared__ float red[64];
    red[j] = s; __syncthreads();
    for (int o = 32; o > 0; o >>= 1) { if (j < o) red[j] = fmaxf(red[j], red[j + o]); __syncthreads(); }
    float mx = red[0]; __syncthreads();
    float e = expf(s - mx);
    red[j] = e; __syncthreads();
    for (int o = 32; o > 0; o >>= 1) { if (j < o) red[j] += red[j + o]; __syncthreads(); }
    g_beta[((b * 64 + i) * 64) + j] = e / red[0];
}

// ---------------------------------------------------------------------------
// K4: A = v @ beta, stored pre-permuted for the reshape
// ---------------------------------------------------------------------------
__global__ __launch_bounds__(256) void av_kernel()
{
    const int b = blockIdx.y;
    const int n0 = blockIdx.x * 64;
    __shared__ float sv[64][65];
    __shared__ float sb_[64][64];
    const int tid = threadIdx.x;

#pragma unroll
    for (int i = 0; i < 16; i++) {
        int idx = tid + i * 256;
        int r = idx >> 6, c = idx & 63;
        sv[r][c] = g_qkv[(size_t)(b * NVOX + n0 + r) * QKVN + 128 + c];
        sb_[r][c] = g_beta[(b * 64 + r) * 64 + c];
    }
    __syncthreads();

    const int lane = tid & 31;
    const int w = tid >> 5;
#pragma unroll
    for (int ii = 0; ii < 8; ii++) {
        int i = w * 8 + ii;
#pragma unroll
        for (int h = 0; h < 2; h++) {
            int n = h * 32 + lane;
            float acc = 0.f;
#pragma unroll
            for (int m = 0; m < 64; m++)
                acc += sv[n][m] * sb_[m][i];
            int ng = n0 + n;
            int p = (i << 8) | (ng >> 6);
            int d = ng & 63;
            g_Ag[(size_t)(b * NVOX + p) * C8 + d] = acc;
        }
    }
}

// ---------------------------------------------------------------------------
extern "C" void kernel_launch(void* const* d_in, const int* in_sizes, int n_in,
                              void* d_out, int out_size)
{
    const float* x   = (const float*)d_in[0];
    const float* g1  = (const float*)d_in[1];
    const float* be1 = (const float*)d_in[2];
    const float* m1  = (const float*)d_in[3];
    const float* v1  = (const float*)d_in[4];
    const float* wq  = (const float*)d_in[5];
    const float* bq  = (const float*)d_in[6];
    const float* wk  = (const float*)d_in[7];
    const float* bk  = (const float*)d_in[8];
    const float* wv  = (const float*)d_in[9];
    const float* bv  = (const float*)d_in[10];
    const float* wp  = (const float*)d_in[11];
    const float* bp  = (const float*)d_in[12];
    const float* g2  = (const float*)d_in[13];
    const float* be2 = (const float*)d_in[14];
    const float* m2  = (const float*)d_in[15];
    const float* v2  = (const float*)d_in[16];
    float* out = (float*)d_out;

    cudaFuncSetAttribute(gemm_qkv,  cudaFuncAttributeMaxDynamicSharedMemorySize, SMEM_QKV);
    cudaFuncSetAttribute(gemm_proj, cudaFuncAttributeMaxDynamicSharedMemorySize, SMEM_PROJ);

    prep_kernel<<<200, 256>>>(g1, be1, m1, v1, wq, bq, wk, bk, wv, bv,
                              wp, bp, g2, be2, m2, v2);

    gemm_qkv<<<(BB * NVOX) / 128, 512, SMEM_QKV>>>(x);

    s_partial_kernel<<<dim3(64, BB), 256>>>();
    softmax_kernel<<<dim3(64, BB), 64>>>();
    av_kernel<<<dim3(NVOX / 64, BB), 256>>>();

    gemm_proj<<<dim3(2, (BB * NVOX) / 128), 512, SMEM_PROJ>>>(out);
}

// round 6
// speedup vs baseline: 2.9536x; 1.0918x over previous
#include <cuda_runtime.h>
#include <cuda_fp16.h>
#include <cstdint>

#define BB    8
#define NVOX  16384
#define CC    512
#define C8    64
#define QKVN  192

// ---------------------------------------------------------------------------
// Scratch (device globals)
// ---------------------------------------------------------------------------
__device__ float g_qkv[BB * NVOX * QKVN];
__device__ float g_spart[BB * 64 * 64 * 64];
__device__ float g_beta[BB * 64 * 64];
__device__ float g_Ag[BB * NVOX * C8];

// Weights pre-split to fp16 hi/lo in exact m16n8k16 B-fragment layout:
// g_W1f: [t(32)][hl(2)][ntile(24)][lane(32)][reg(2)][half(2)]   (K=512, N=192)
// g_W2f: [t(4)] [hl(2)][ntile(64)][lane(32)][reg(2)][half(2)]   (K=64,  N=512)
__device__ __half g_W1f[512 * 192 * 2];
__device__ float  g_b1[QKVN];
__device__ __half g_W2f[64 * 512 * 2];
__device__ float  g_b2[CC];

// ---------------------------------------------------------------------------
__device__ __forceinline__ void cpasync16(void* sdst, const void* g) {
    unsigned s = (unsigned)__cvta_generic_to_shared(sdst);
    asm volatile("cp.async.cg.shared.global [%0], [%1], 16;\n" :: "r"(s), "l"(g));
}
__device__ __forceinline__ void cpcommit() { asm volatile("cp.async.commit_group;\n"); }
__device__ __forceinline__ void cpwait0()  { asm volatile("cp.async.wait_group 0;\n"); }

__device__ __forceinline__ void ldmat4(uint32_t* r, const void* p) {
    uint32_t a = (uint32_t)__cvta_generic_to_shared(p);
    asm volatile("ldmatrix.sync.aligned.m8n8.x4.shared.b16 {%0,%1,%2,%3}, [%4];"
        : "=r"(r[0]), "=r"(r[1]), "=r"(r[2]), "=r"(r[3]) : "r"(a));
}

// D += A(f16) * B(f16), fp32 accum; m16n8k16
__device__ __forceinline__ void mma16(float* d, const uint32_t* a, const uint32_t* b) {
    asm volatile(
        "mma.sync.aligned.m16n8k16.row.col.f32.f16.f16.f32 "
        "{%0,%1,%2,%3},{%4,%5,%6,%7},{%8,%9},{%0,%1,%2,%3};"
        : "+f"(d[0]), "+f"(d[1]), "+f"(d[2]), "+f"(d[3])
        : "r"(a[0]), "r"(a[1]), "r"(a[2]), "r"(a[3]), "r"(b[0]), "r"(b[1]));
}

// fragment index helpers (B operand k16n8): k within 16-chunk, n within tile-8
__device__ __forceinline__ int bfrag_idx(int t, int hl, int ntile, int NT, int k, int n) {
    int lane = ((n & 7) << 2) | ((k & 7) >> 1);
    int reg = (k >> 3) & 1;
    int halfsel = k & 1;
    return ((((t * 2 + hl) * NT + ntile) * 32 + lane) * 2 + reg) * 2 + halfsel;
}

// ---------------------------------------------------------------------------
// K0: prep. Blocks 0..191: QKV col n -> g_W1f frags + b1. 192..199: proj.
// ---------------------------------------------------------------------------
__global__ __launch_bounds__(256) void prep_kernel(
    const float* __restrict__ g1, const float* __restrict__ be1,
    const float* __restrict__ m1, const float* __restrict__ v1,
    const float* __restrict__ wq, const float* __restrict__ bq,
    const float* __restrict__ wk, const float* __restrict__ bk,
    const float* __restrict__ wv, const float* __restrict__ bv,
    const float* __restrict__ wp, const float* __restrict__ bp,
    const float* __restrict__ g2, const float* __restrict__ be2,
    const float* __restrict__ m2, const float* __restrict__ v2)
{
    __shared__ float sA[CC], sT[CC];
    __shared__ float red[256];
    const int blk = blockIdx.x;
    const int tid = threadIdx.x;

    if (blk < 192) {
        for (int k = tid; k < CC; k += 256) {
            float a = g1[k] * rsqrtf(v1[k] + 1e-3f);
            sA[k] = a;
            sT[k] = be1[k] - m1[k] * a;
        }
        __syncthreads();
        const int n = blk;
        const float* w = (n < 64) ? wq : (n < 128) ? wk : wv;
        const int j = n & 63;
        const int ntile = n >> 3;
        float part = 0.f;
        for (int k = tid; k < CC; k += 256) {
            float wv_ = w[k * 64 + j];
            float val = sA[k] * wv_;
            __half hi = __float2half(val);
            __half lo = __float2half(val - __half2float(hi));
            int t = k >> 4;
            g_W1f[bfrag_idx(t, 0, ntile, 24, k & 15, n & 7)] = hi;
            g_W1f[bfrag_idx(t, 1, ntile, 24, k & 15, n & 7)] = lo;
            part += sT[k] * wv_;
        }
        red[tid] = part; __syncthreads();
        for (int o = 128; o > 0; o >>= 1) { if (tid < o) red[tid] += red[tid + o]; __syncthreads(); }
        if (tid == 0) {
            float b0 = (n < 64) ? bq[j] : (n < 128) ? bk[j] : bv[j];
            g_b1[n] = b0 + red[0];
        }
    } else {
        for (int k = tid; k < CC; k += 256) {
            float a = g2[k] * rsqrtf(v2[k] + 1e-3f);
            sA[k] = a;
            sT[k] = be2[k] - m2[k] * a;
        }
        __syncthreads();
        const int n0 = (blk - 192) * 64;
        for (int idx = tid; idx < 64 * 64; idx += 256) {
            int n = n0 + (idx >> 6), k = idx & 63;
            float val = wp[k * CC + n] * sA[n];
            __half hi = __float2half(val);
            __half lo = __float2half(val - __half2float(hi));
            int t = k >> 4;
            g_W2f[bfrag_idx(t, 0, n >> 3, 64, k & 15, n & 7)] = hi;
            g_W2f[bfrag_idx(t, 1, n >> 3, 64, k & 15, n & 7)] = lo;
        }
        if (tid < 64) {
            int n = n0 + tid;
            g_b2[n] = bp[n] * sA[n] + sT[n];
        }
    }
}

// ---------------------------------------------------------------------------
// K1: QKV GEMM fp16x3, m16n8k16. CTA: 64m x 192n, K=512 (32 chunks of 16).
// 256 threads = 8 warps (2m x 4n), warp tile 32m x 48n. 2 CTAs/SM for overlap.
// A smem/buf: [hl(2)][row(64)][24 halfs] = 3072. B smem/buf: frag layout 6144.
// ---------------------------------------------------------------------------
#define ABUF_Q 3072
#define SMEM_QKV ((2 * ABUF_Q + 2 * 6144) * 2)   // 36864 B

__global__ __launch_bounds__(256, 2) void gemm_qkv(const float* __restrict__ X)
{
    extern __shared__ __half smh[];
    __half* Ab0 = smh;
    __half* Ab1 = smh + ABUF_Q;
    __half* Bb0 = smh + 2 * ABUF_Q;
    __half* Bb1 = smh + 2 * ABUF_Q + 6144;

    const int tid = threadIdx.x;
    const int wid = tid >> 5, lane = tid & 31;
    const int wm = wid & 1, wn = wid >> 1;
    const int m0 = blockIdx.x * 64;

    const int ar = tid >> 2;            // row 0..63
    const int ac = (tid & 3) * 4;       // col 0,4,8,12

    float acc[2][6][4];
#pragma unroll
    for (int i = 0; i < 2; i++)
#pragma unroll
        for (int j = 0; j < 6; j++)
#pragma unroll
            for (int q = 0; q < 4; q++) acc[i][j][q] = 0.f;

    float4 areg;

    auto ldgA = [&](int t) {
        areg = *(const float4*)(X + (size_t)(m0 + ar) * CC + t * 16 + ac);
    };
    auto stsA = [&](__half* Ab) {
        float vv[4] = {areg.x, areg.y, areg.z, areg.w};
        __half h[4], l[4];
#pragma unroll
        for (int q = 0; q < 4; q++) {
            h[q] = __float2half(vv[q]);
            l[q] = __float2half(vv[q] - __half2float(h[q]));
        }
        *(uint2*)&Ab[ar * 24 + ac] = *(uint2*)h;
        *(uint2*)&Ab[(64 + ar) * 24 + ac] = *(uint2*)l;
    };
    auto cpB = [&](int t, __half* Bb) {
        const __half* src = g_W1f + (size_t)t * 6144;
#pragma unroll
        for (int i = 0; i < 3; i++) {
            int v = tid + i * 256;
            cpasync16(&Bb[v * 8], src + v * 8);
        }
        cpcommit();
    };
    auto compute = [&](const __half* Ab, const __half* Bb) {
        uint32_t af[2][2][4];
#pragma unroll
        for (int mi = 0; mi < 2; mi++)
#pragma unroll
            for (int hl = 0; hl < 2; hl++)
                ldmat4(af[mi][hl],
                       &Ab[(hl * 64 + wm * 32 + mi * 16 + (lane & 15)) * 24 + (lane >> 4) * 8]);
#pragma unroll
        for (int ni = 0; ni < 6; ni++) {
            int nt = wn * 6 + ni;
            uint32_t bh[2], bl[2];
            *(uint2*)bh = *(const uint2*)&Bb[((0 * 24 + nt) * 32 + lane) * 4];
            *(uint2*)bl = *(const uint2*)&Bb[((1 * 24 + nt) * 32 + lane) * 4];
#pragma unroll
            for (int mi = 0; mi < 2; mi++) {
                mma16(acc[mi][ni], af[mi][0], bh);
                mma16(acc[mi][ni], af[mi][0], bl);
                mma16(acc[mi][ni], af[mi][1], bh);
            }
        }
    };

    ldgA(0);
    cpB(0, Bb0);
    stsA(Ab0);

    for (int t = 0; t < 32; t++) {
        __half* Ac = (t & 1) ? Ab1 : Ab0;
        __half* Bc = (t & 1) ? Bb1 : Bb0;
        __half* An = (t & 1) ? Ab0 : Ab1;
        __half* Bn = (t & 1) ? Bb0 : Bb1;
        if (t + 1 < 32) ldgA(t + 1);
        cpwait0();
        __syncthreads();
        if (t + 1 < 32) cpB(t + 1, Bn);
        compute(Ac, Bc);
        if (t + 1 < 32) stsA(An);
    }

    const int gid = lane >> 2, tg = lane & 3;
#pragma unroll
    for (int mi = 0; mi < 2; mi++) {
        int r0 = m0 + wm * 32 + mi * 16 + gid;
#pragma unroll
        for (int ni = 0; ni < 6; ni++) {
            int col = wn * 48 + ni * 8 + tg * 2;
            float b0 = g_b1[col], b1 = g_b1[col + 1];
            float2 v0 = make_float2(acc[mi][ni][0] + b0, acc[mi][ni][1] + b1);
            float2 v1 = make_float2(acc[mi][ni][2] + b0, acc[mi][ni][3] + b1);
            *(float2*)&g_qkv[(size_t)r0 * QKVN + col] = v0;
            *(float2*)&g_qkv[(size_t)(r0 + 8) * QKVN + col] = v1;
        }
    }
}

// ---------------------------------------------------------------------------
// K5: proj GEMM fp16x3. CTA: 64m x 256n (nh half), K=64 (4 chunks of 16).
// 256 threads = 8 warps (2m x 4n), warp tile 32m x 64n. 2 CTAs/SM.
// B smem/buf: [hl(2)][ntile_local(32)][lane][reg][half] = 8192 halfs.
// ---------------------------------------------------------------------------
#define SMEM_PROJ ((2 * ABUF_Q + 2 * 8192) * 2)  // 45056 B

__global__ __launch_bounds__(256, 2) void gemm_proj(float* __restrict__ Out)
{
    extern __shared__ __half smh[];
    __half* Ab0 = smh;
    __half* Ab1 = smh + ABUF_Q;
    __half* Bb0 = smh + 2 * ABUF_Q;
    __half* Bb1 = smh + 2 * ABUF_Q + 8192;

    const int tid = threadIdx.x;
    const int wid = tid >> 5, lane = tid & 31;
    const int wm = wid & 1, wn = wid >> 1;
    const int nh = blockIdx.x;
    const int m0 = blockIdx.y * 64;

    const int ar = tid >> 2;
    const int ac = (tid & 3) * 4;

    float acc[2][8][4];
#pragma unroll
    for (int i = 0; i < 2; i++)
#pragma unroll
        for (int j = 0; j < 8; j++)
#pragma unroll
            for (int q = 0; q < 4; q++) acc[i][j][q] = 0.f;

    float4 areg;

    auto ldgA = [&](int t) {
        areg = *(const float4*)(g_Ag + (size_t)(m0 + ar) * C8 + t * 16 + ac);
    };
    auto stsA = [&](__half* Ab) {
        float vv[4] = {areg.x, areg.y, areg.z, areg.w};
        __half h[4], l[4];
#pragma unroll
        for (int q = 0; q < 4; q++) {
            h[q] = __float2half(vv[q]);
            l[q] = __float2half(vv[q] - __half2float(h[q]));
        }
        *(uint2*)&Ab[ar * 24 + ac] = *(uint2*)h;
        *(uint2*)&Ab[(64 + ar) * 24 + ac] = *(uint2*)l;
    };
    auto cpB = [&](int t, __half* Bb) {
#pragma unroll
        for (int hl = 0; hl < 2; hl++) {
            const __half* src = g_W2f + ((size_t)(t * 2 + hl) * 64 + nh * 32) * 128;
#pragma unroll
            for (int i = 0; i < 2; i++) {
                int v = tid + i * 256;
                cpasync16(&Bb[hl * 4096 + v * 8], src + v * 8);
            }
        }
        cpcommit();
    };
    auto compute = [&](const __half* Ab, const __half* Bb) {
        uint32_t af[2][2][4];
#pragma unroll
        for (int mi = 0; mi < 2; mi++)
#pragma unroll
            for (int hl = 0; hl < 2; hl++)
                ldmat4(af[mi][hl],
                       &Ab[(hl * 64 + wm * 32 + mi * 16 + (lane & 15)) * 24 + (lane >> 4) * 8]);
#pragma unroll
        for (int ni = 0; ni < 8; ni++) {
            int ntl = wn * 8 + ni;
            uint32_t bh[2], bl[2];
            *(uint2*)bh = *(const uint2*)&Bb[(ntl * 32 + lane) * 4];
            *(uint2*)bl = *(const uint2*)&Bb[4096 + (ntl * 32 + lane) * 4];
#pragma unroll
            for (int mi = 0; mi < 2; mi++) {
                mma16(acc[mi][ni], af[mi][0], bh);
                mma16(acc[mi][ni], af[mi][0], bl);
                mma16(acc[mi][ni], af[mi][1], bh);
            }
        }
    };

    ldgA(0);
    cpB(0, Bb0);
    stsA(Ab0);

    for (int t = 0; t < 4; t++) {
        __half* Ac = (t & 1) ? Ab1 : Ab0;
        __half* Bc = (t & 1) ? Bb1 : Bb0;
        __half* An = (t & 1) ? Ab0 : Ab1;
        __half* Bn = (t & 1) ? Bb0 : Bb1;
        if (t + 1 < 4) ldgA(t + 1);
        cpwait0();
        __syncthreads();
        if (t + 1 < 4) cpB(t + 1, Bn);
        compute(Ac, Bc);
        if (t + 1 < 4) stsA(An);
    }

    const int gid = lane >> 2, tg = lane & 3;
#pragma unroll
    for (int mi = 0; mi < 2; mi++) {
        int r0 = m0 + wm * 32 + mi * 16 + gid;
#pragma unroll
        for (int ni = 0; ni < 8; ni++) {
            int col = nh * 256 + wn * 64 + ni * 8 + tg * 2;
            float b0 = g_b2[col], b1 = g_b2[col + 1];
            float2 v0 = make_float2(acc[mi][ni][0] + b0, acc[mi][ni][1] + b1);
            float2 v1 = make_float2(acc[mi][ni][2] + b0, acc[mi][ni][3] + b1);
            *(float2*)&Out[(size_t)r0 * CC + col] = v0;
            *(float2*)&Out[(size_t)(r0 + 8) * CC + col] = v1;
        }
    }
}

// ---------------------------------------------------------------------------
// K2: s partials, fp32 split-K.  s[b,i,j] = sum_n q[b,n,i]*k[b,n,j]
// ---------------------------------------------------------------------------
__global__ __launch_bounds__(256) void s_partial_kernel()
{
    const int sl = blockIdx.x, b = blockIdx.y;
    __shared__ float sq[64][68], sk[64][68];
    const int tid = threadIdx.x;
    const int jj = tid & 63;
    const int ig = tid >> 6;

    float acc[16];
#pragma unroll
    for (int u = 0; u < 16; u++) acc[u] = 0.f;

    for (int c4 = 0; c4 < 4; c4++) {
        int nb = sl * 256 + c4 * 64;
        __syncthreads();
#pragma unroll
        for (int i = 0; i < 16; i++) {
            int idx = tid + i * 256;
            int r = idx >> 6, c = idx & 63;
            const float* row = g_qkv + (size_t)(b * NVOX + nb + r) * QKVN;
            sq[r][c] = row[c];
            sk[r][c] = row[64 + c];
        }
        __syncthreads();
        for (int n = 0; n < 64; n++) {
            float kv = sk[n][jj];
            const float4* qp = (const float4*)&sq[n][ig * 16];
            float4 q0 = qp[0], q1 = qp[1], q2 = qp[2], q3 = qp[3];
            acc[0]  += q0.x * kv; acc[1]  += q0.y * kv; acc[2]  += q0.z * kv; acc[3]  += q0.w * kv;
            acc[4]  += q1.x * kv; acc[5]  += q1.y * kv; acc[6]  += q1.z * kv; acc[7]  += q1.w * kv;
            acc[8]  += q2.x * kv; acc[9]  += q2.y * kv; acc[10] += q2.z * kv; acc[11] += q2.w * kv;
            acc[12] += q3.x * kv; acc[13] += q3.y * kv; acc[14] += q3.z * kv; acc[15] += q3.w * kv;
        }
    }
#pragma unroll
    for (int u = 0; u < 16; u++) {
        int i = ig * 16 + u;
        g_spart[(((b * 64 + sl) * 64) + i) * 64 + jj] = acc[u];
    }
}

// ---------------------------------------------------------------------------
// K3: deterministic reduce + row softmax
// ---------------------------------------------------------------------------
__global__ __launch_bounds__(64) void softmax_kernel()
{
    const int i = blockIdx.x, b = blockIdx.y;
    const int j = threadIdx.x;
    float s = 0.f;
    for (int sl = 0; sl < 64; sl++)
        s += g_spart[(((b * 64 + sl) * 64) + i) * 64 + j];

    __shared__ float red[64];
    red[j] = s; __syncthreads();
    for (int o = 32; o > 0; o >>= 1) { if (j < o) red[j] = fmaxf(red[j], red[j + o]); __syncthreads(); }
    float mx = red[0]; __syncthreads();
    float e = expf(s - mx);
    red[j] = e; __syncthreads();
    for (int o = 32; o > 0; o >>= 1) { if (j < o) red[j] += red[j + o]; __syncthreads(); }
    g_beta[((b * 64 + i) * 64) + j] = e / red[0];
}

// ---------------------------------------------------------------------------
// K4: A = v @ beta, stored pre-permuted for the reshape
// ---------------------------------------------------------------------------
__global__ __launch_bounds__(256) void av_kernel()
{
    const int b = blockIdx.y;
    const int n0 = blockIdx.x * 64;
    __shared__ float sv[64][65];
    __shared__ float sb_[64][64];
    const int tid = threadIdx.x;

#pragma unroll
    for (int i = 0; i < 16; i++) {
        int idx = tid + i * 256;
        int r = idx >> 6, c = idx & 63;
        sv[r][c] = g_qkv[(size_t)(b * NVOX + n0 + r) * QKVN + 128 + c];
        sb_[r][c] = g_beta[(b * 64 + r) * 64 + c];
    }
    __syncthreads();

    const int lane = tid & 31;
    const int w = tid >> 5;
#pragma unroll
    for (int ii = 0; ii < 8; ii++) {
        int i = w * 8 + ii;
#pragma unroll
        for (int h = 0; h < 2; h++) {
            int n = h * 32 + lane;
            float acc = 0.f;
#pragma unroll
            for (int m = 0; m < 64; m++)
                acc += sv[n][m] * sb_[m][i];
            int ng = n0 + n;
            int p = (i << 8) | (ng >> 6);
            int d = ng & 63;
            g_Ag[(size_t)(b * NVOX + p) * C8 + d] = acc;
        }
    }
}

// ---------------------------------------------------------------------------
extern "C" void kernel_launch(void* const* d_in, const int* in_sizes, int n_in,
                              void* d_out, int out_size)
{
    const float* x   = (const float*)d_in[0];
    const float* g1  = (const float*)d_in[1];
    const float* be1 = (const float*)d_in[2];
    const float* m1  = (const float*)d_in[3];
    const float* v1  = (const float*)d_in[4];
    const float* wq  = (const float*)d_in[5];
    const float* bq  = (const float*)d_in[6];
    const float* wk  = (const float*)d_in[7];
    const float* bk  = (const float*)d_in[8];
    const float* wv  = (const float*)d_in[9];
    const float* bv  = (const float*)d_in[10];
    const float* wp  = (const float*)d_in[11];
    const float* bp  = (const float*)d_in[12];
    const float* g2  = (const float*)d_in[13];
    const float* be2 = (const float*)d_in[14];
    const float* m2  = (const float*)d_in[15];
    const float* v2  = (const float*)d_in[16];
    float* out = (float*)d_out;

    prep_kernel<<<200, 256>>>(g1, be1, m1, v1, wq, bq, wk, bk, wv, bv,
                              wp, bp, g2, be2, m2, v2);

    // QKV: M=131072 in 64-row CTAs, full N=192, 2 CTAs/SM
    gemm_qkv<<<(BB * NVOX) / 64, 256, SMEM_QKV>>>(x);

    s_partial_kernel<<<dim3(64, BB), 256>>>();
    softmax_kernel<<<dim3(64, BB), 64>>>();
    av_kernel<<<dim3(NVOX / 64, BB), 256>>>();

    // proj: M=131072 in 64-row CTAs, N=512 in 2 halves, 2 CTAs/SM
    gemm_proj<<<dim3(2, (BB * NVOX) / 64), 256, SMEM_PROJ>>>(out);
}